// round 5
// baseline (speedup 1.0000x reference)
#include <cuda_runtime.h>
#include <math.h>
#include <stdint.h>

// Problem constants
#define BB   2
#define SS   2048
#define DIMM 4096
#define NHH  32
#define NKVV 8
#define HDD  128
#define MROWS (BB*SS)            // 4096
#define OUT_ELEMS   (MROWS*DIMM) // 16777216
#define KV_ELEMS    (MROWS*NKVV*HDD) // 4194304

// Scratch (device globals -- no allocation allowed)
__device__ float g_q[(size_t)MROWS * DIMM];     // roped Q, (b,s,h,d)
__device__ float g_ctx[(size_t)MROWS * DIMM];   // ctx (tf32-rounded by attn epilogue)
__device__ float g_xc[(size_t)MROWS * DIMM];    // x, tf32-rounded
__device__ float g_wqc[(size_t)DIMM * DIMM];    // wq, tf32-rounded
__device__ float g_wkc[(size_t)DIMM * NKVV * HDD];
__device__ float g_wvc[(size_t)DIMM * NKVV * HDD];
__device__ float g_woc[(size_t)DIMM * DIMM];

__device__ __forceinline__ uint32_t f2tf32(float f) {
    uint32_t u;
    asm volatile("cvt.rna.tf32.f32 %0, %1;" : "=r"(u) : "f"(f));
    return u;
}

__device__ __forceinline__ void cp_async16(uint32_t dst, const void* src) {
    asm volatile("cp.async.ca.shared.global [%0], [%1], 16;\n" :: "r"(dst), "l"(src));
}
__device__ __forceinline__ void cp_commit() {
    asm volatile("cp.async.commit_group;\n");
}
template <int W>
__device__ __forceinline__ void cp_wait() {
    asm volatile("cp.async.wait_group %0;\n" :: "n"(W));
}

// ----------------------------------------------------------------------------
// Elementwise tf32 rounding: out[i] = tf32(in[i]) stored as fp32 bits.
// n must be a multiple of 4.
// ----------------------------------------------------------------------------
__global__ void cvt_tf32_kernel(const float* __restrict__ in,
                                float* __restrict__ out, int n4)
{
    int i = blockIdx.x * blockDim.x + threadIdx.x;
    if (i >= n4) return;
    float4 v = ((const float4*)in)[i];
    float4 o;
    o.x = __uint_as_float(f2tf32(v.x));
    o.y = __uint_as_float(f2tf32(v.y));
    o.z = __uint_as_float(f2tf32(v.z));
    o.w = __uint_as_float(f2tf32(v.w));
    ((float4*)out)[i] = o;
}

// ----------------------------------------------------------------------------
// TF32 tensor-core GEMM, 3-stage cp.async pipeline.
// C[M,N] = A[M,K]*B[K,N], row-major; A,B already tf32-rounded fp32.
// CTA tile 128x256, BK=32, 256 threads = 8 warps (2M x 4N), warp tile 64x64.
// A smem [128][36], B smem [32][264] (both conflict-free for frag reads).
// Requires M%128==0, N%256==0, K%32==0.
// ----------------------------------------------------------------------------
#define BK 32
#define A_STRIDE 36
#define B_STRIDE 264
#define A_STAGE (128 * A_STRIDE)
#define B_STAGE (BK * B_STRIDE)
#define STAGE_FLOATS (A_STAGE + B_STAGE)
#define NSTAGE 3
#define GEMM_SMEM_FLOATS (NSTAGE * STAGE_FLOATS)

__global__ __launch_bounds__(256) void gemm_tf32_kernel(
    const float* __restrict__ A, const float* __restrict__ Bm,
    float* __restrict__ C, int M, int N, int K)
{
    extern __shared__ float sm[];

    const int tid   = threadIdx.x;
    const int lane  = tid & 31;
    const int warp  = tid >> 5;
    const int warpM = warp >> 2;          // 0..1
    const int warpN = warp & 3;           // 0..3
    const int bm = blockIdx.y * 128;
    const int bn = blockIdx.x * 256;

    const int qk = lane & 3;
    const int qr = lane >> 2;

    const int ntiles = K / BK;

    float acc[4][8][4];
#pragma unroll
    for (int i = 0; i < 4; i++)
#pragma unroll
        for (int j = 0; j < 8; j++)
#pragma unroll
            for (int r = 0; r < 4; r++) acc[i][j][r] = 0.0f;

    auto load_tile = [&](int t, int st) {
        const float* Asrc = A + (size_t)bm * K + t * BK;
        float* Ad = sm + st * STAGE_FLOATS;
#pragma unroll
        for (int l = 0; l < 4; l++) {
            int flat = l * 256 + tid;
            int m  = flat >> 3;           // 0..127
            int kg = flat & 7;            // 0..7
            uint32_t dst = (uint32_t)__cvta_generic_to_shared(Ad + m * A_STRIDE + kg * 4);
            cp_async16(dst, Asrc + (size_t)m * K + kg * 4);
        }
        const float* Bsrc = Bm + (size_t)(t * BK) * N + bn;
        float* Bd = sm + st * STAGE_FLOATS + A_STAGE;
#pragma unroll
        for (int l = 0; l < 8; l++) {
            int flat = l * 256 + tid;
            int k  = flat >> 6;           // 0..31
            int ng = flat & 63;           // 0..63
            uint32_t dst = (uint32_t)__cvta_generic_to_shared(Bd + k * B_STRIDE + ng * 4);
            cp_async16(dst, Bsrc + (size_t)k * N + ng * 4);
        }
        cp_commit();
    };

    load_tile(0, 0);
    if (ntiles > 1) load_tile(1, 1);

    for (int t = 0; t < ntiles; t++) {
        const int st = t % NSTAGE;
        if (t + 2 < ntiles) {
            load_tile(t + 2, (t + 2) % NSTAGE);
            cp_wait<2>();
        } else if (t + 1 < ntiles) {
            cp_wait<1>();
        } else {
            cp_wait<0>();
        }
        __syncthreads();

        const uint32_t* As = (const uint32_t*)(sm + st * STAGE_FLOATS);
        const uint32_t* Bs = (const uint32_t*)(sm + st * STAGE_FLOATS + A_STAGE);

#pragma unroll
        for (int kk = 0; kk < BK; kk += 8) {
            uint32_t af[4][4], bf[8][2];
#pragma unroll
            for (int mf = 0; mf < 4; mf++) {
                int row = warpM * 64 + mf * 16 + qr;
                af[mf][0] = As[row * A_STRIDE + kk + qk];
                af[mf][1] = As[(row + 8) * A_STRIDE + kk + qk];
                af[mf][2] = As[row * A_STRIDE + kk + qk + 4];
                af[mf][3] = As[(row + 8) * A_STRIDE + kk + qk + 4];
            }
#pragma unroll
            for (int nf = 0; nf < 8; nf++) {
                int col = warpN * 64 + nf * 8 + qr;
                bf[nf][0] = Bs[(kk + qk) * B_STRIDE + col];
                bf[nf][1] = Bs[(kk + qk + 4) * B_STRIDE + col];
            }
#pragma unroll
            for (int mf = 0; mf < 4; mf++)
#pragma unroll
                for (int nf = 0; nf < 8; nf++) {
                    asm volatile(
                        "mma.sync.aligned.m16n8k8.row.col.f32.tf32.tf32.f32 "
                        "{%0,%1,%2,%3}, {%4,%5,%6,%7}, {%8,%9}, {%0,%1,%2,%3};"
                        : "+f"(acc[mf][nf][0]), "+f"(acc[mf][nf][1]),
                          "+f"(acc[mf][nf][2]), "+f"(acc[mf][nf][3])
                        : "r"(af[mf][0]), "r"(af[mf][1]),
                          "r"(af[mf][2]), "r"(af[mf][3]),
                          "r"(bf[nf][0]), "r"(bf[nf][1]));
                }
        }
        __syncthreads();
    }

    // epilogue
#pragma unroll
    for (int mf = 0; mf < 4; mf++) {
        int row = bm + warpM * 64 + mf * 16 + qr;
#pragma unroll
        for (int nf = 0; nf < 8; nf++) {
            int col = bn + warpN * 64 + nf * 8 + 2 * qk;
            float2* p0 = (float2*)(C + (size_t)row * N + col);
            float2* p1 = (float2*)(C + (size_t)(row + 8) * N + col);
            *p0 = make_float2(acc[mf][nf][0], acc[mf][nf][1]);
            *p1 = make_float2(acc[mf][nf][2], acc[mf][nf][3]);
        }
    }
}

// ----------------------------------------------------------------------------
// RoPE, in place. data layout: [rows][heads*128], pairs are (2i, 2i+1).
// ----------------------------------------------------------------------------
__global__ void rope_kernel(float* __restrict__ data,
                            const float* __restrict__ fc,
                            int rows, int heads)
{
    int idx = blockIdx.x * blockDim.x + threadIdx.x;
    int total = rows * heads * 64;
    if (idx >= total) return;
    int i = idx & 63;
    int h = (idx >> 6) % heads;
    int row = idx / (heads * 64);
    int s = row & (SS - 1);
    float c = fc[(size_t)s * 128 + i * 2 + 0];
    float sn = fc[(size_t)s * 128 + i * 2 + 1];
    float* p = data + (size_t)row * heads * HDD + h * HDD + i * 2;
    float xr = p[0], xi = p[1];
    p[0] = xr * c - xi * sn;
    p[1] = xr * sn + xi * c;
}

// ----------------------------------------------------------------------------
// Flash-style GQA attention, fp32. Epilogue rounds ctx to tf32 (feeds wo GEMM).
// ----------------------------------------------------------------------------
#define ATTN_SMEM_FLOATS (128*65 + 128*65 + 64*128 + 64*65)
__global__ __launch_bounds__(256) void attn_kernel(
    const float* __restrict__ Q, const float* __restrict__ K,
    const float* __restrict__ V, float* __restrict__ O)
{
    extern __shared__ float sm[];
    float* Qs = sm;                // [128][65]
    float* Ks = Qs + 128 * 65;     // [128][65]
    float* Vs = Ks + 128 * 65;     // [64][128]
    float* Pt = Vs + 64 * 128;     // [64][65]

    const int tid = threadIdx.x;
    const int ty = tid >> 4;
    const int tx = tid & 15;
    const int qtile = blockIdx.x;
    const int h = blockIdx.y;
    const int b = blockIdx.z;
    const int g = h >> 2;        // N_REP = 4

    const float* qbase = Q + ((size_t)b * SS + qtile * 64) * DIMM + h * HDD;
    const float* kbase = K + (size_t)b * SS * (NKVV * HDD) + g * HDD;
    const float* vbase = V + (size_t)b * SS * (NKVV * HDD) + g * HDD;

    for (int idx = tid; idx < 64 * 128; idx += 256) {
        int r = idx >> 7, d = idx & 127;
        Qs[d * 65 + r] = qbase[(size_t)r * DIMM + d];
    }

    const float scale = 0.08838834764831845f;
    float m[4], l[4], acc[4][8];
#pragma unroll
    for (int i = 0; i < 4; i++) {
        m[i] = -1e30f;
        l[i] = 0.0f;
#pragma unroll
        for (int j = 0; j < 8; j++) acc[i][j] = 0.0f;
    }

    for (int kt = 0; kt < SS / 64; kt++) {
        __syncthreads();
        for (int idx = tid; idx < 64 * 128; idx += 256) {
            int r = idx >> 7, d = idx & 127;
            Ks[d * 65 + r] = kbase[(size_t)(kt * 64 + r) * (NKVV * HDD) + d];
            Vs[r * 128 + d] = vbase[(size_t)(kt * 64 + r) * (NKVV * HDD) + d];
        }
        __syncthreads();

        float s[4][4];
#pragma unroll
        for (int i = 0; i < 4; i++)
#pragma unroll
            for (int j = 0; j < 4; j++) s[i][j] = 0.0f;

        for (int kk = 0; kk < 128; kk++) {
            float ra[4], rb[4];
#pragma unroll
            for (int i = 0; i < 4; i++) ra[i] = Qs[kk * 65 + ty * 4 + i];
#pragma unroll
            for (int j = 0; j < 4; j++) rb[j] = Ks[kk * 65 + tx * 4 + j];
#pragma unroll
            for (int i = 0; i < 4; i++)
#pragma unroll
                for (int j = 0; j < 4; j++)
                    s[i][j] = fmaf(ra[i], rb[j], s[i][j]);
        }

#pragma unroll
        for (int i = 0; i < 4; i++) {
            float mx = s[i][0];
#pragma unroll
            for (int j = 1; j < 4; j++) mx = fmaxf(mx, s[i][j]);
            mx *= scale;
#pragma unroll
            for (int off = 8; off > 0; off >>= 1)
                mx = fmaxf(mx, __shfl_xor_sync(0xffffffffu, mx, off));
            float mnew = fmaxf(m[i], mx);
            float corr = __expf(m[i] - mnew);
            float ls = 0.0f;
#pragma unroll
            for (int j = 0; j < 4; j++) {
                float p = __expf(s[i][j] * scale - mnew);
                Pt[(tx * 4 + j) * 65 + ty * 4 + i] = p;
                ls += p;
            }
#pragma unroll
            for (int off = 8; off > 0; off >>= 1)
                ls += __shfl_xor_sync(0xffffffffu, ls, off);
            l[i] = l[i] * corr + ls;
            m[i] = mnew;
#pragma unroll
            for (int jj = 0; jj < 8; jj++) acc[i][jj] *= corr;
        }
        __syncthreads();

        for (int k = 0; k < 64; k++) {
            float pa[4];
#pragma unroll
            for (int i = 0; i < 4; i++) pa[i] = Pt[k * 65 + ty * 4 + i];
            float vb[8];
#pragma unroll
            for (int jj = 0; jj < 8; jj++) vb[jj] = Vs[k * 128 + tx + 16 * jj];
#pragma unroll
            for (int i = 0; i < 4; i++)
#pragma unroll
                for (int jj = 0; jj < 8; jj++)
                    acc[i][jj] = fmaf(pa[i], vb[jj], acc[i][jj]);
        }
    }

    // ctx written tf32-rounded (consumed only by wo GEMM)
    float* obase = O + ((size_t)b * SS + qtile * 64) * DIMM + h * HDD;
#pragma unroll
    for (int i = 0; i < 4; i++) {
        float inv = 1.0f / l[i];
#pragma unroll
        for (int jj = 0; jj < 8; jj++)
            obase[(size_t)(ty * 4 + i) * DIMM + tx + 16 * jj] =
                __uint_as_float(f2tf32(acc[i][jj] * inv));
    }
}

// ----------------------------------------------------------------------------
// Launch
// ----------------------------------------------------------------------------
extern "C" void kernel_launch(void* const* d_in, const int* in_sizes, int n_in,
                              void* d_out, int out_size)
{
    const float* x  = (const float*)d_in[0];
    const float* fc = (const float*)d_in[1];
    const float* wq = (const float*)d_in[2];
    const float* wk = (const float*)d_in[3];
    const float* wv = (const float*)d_in[4];
    const float* wo = (const float*)d_in[5];

    float* out  = (float*)d_out;                 // (b,s,DIM)
    float* kout = out + (size_t)OUT_ELEMS;       // new_k
    float* vout = kout + (size_t)KV_ELEMS;       // new_v

    float *qptr, *ctxptr, *xc, *wqc, *wkc, *wvc, *woc;
    cudaGetSymbolAddress((void**)&qptr, g_q);
    cudaGetSymbolAddress((void**)&ctxptr, g_ctx);
    cudaGetSymbolAddress((void**)&xc, g_xc);
    cudaGetSymbolAddress((void**)&wqc, g_wqc);
    cudaGetSymbolAddress((void**)&wkc, g_wkc);
    cudaGetSymbolAddress((void**)&wvc, g_wvc);
    cudaGetSymbolAddress((void**)&woc, g_woc);

    // Pre-convert inputs to tf32-rounded fp32
    {
        int n4x = OUT_ELEMS / 4;
        cvt_tf32_kernel<<<(n4x + 255) / 256, 256>>>(x, xc, n4x);
        int n4w = (DIMM * DIMM) / 4;
        cvt_tf32_kernel<<<(n4w + 255) / 256, 256>>>(wq, wqc, n4w);
        cvt_tf32_kernel<<<(n4w + 255) / 256, 256>>>(wo, woc, n4w);
        int n4k = (DIMM * NKVV * HDD) / 4;
        cvt_tf32_kernel<<<(n4k + 255) / 256, 256>>>(wk, wkc, n4k);
        cvt_tf32_kernel<<<(n4k + 255) / 256, 256>>>(wv, wvc, n4k);
    }

    size_t gemm_smem = GEMM_SMEM_FLOATS * sizeof(float); // ~155 KB
    cudaFuncSetAttribute(gemm_tf32_kernel,
                         cudaFuncAttributeMaxDynamicSharedMemorySize,
                         (int)gemm_smem);

    // Q/K/V projections
    {
        dim3 gq(DIMM / 256, MROWS / 128);
        gemm_tf32_kernel<<<gq, 256, gemm_smem>>>(xc, wqc, qptr, MROWS, DIMM, DIMM);
        dim3 gkv((NKVV * HDD) / 256, MROWS / 128);
        gemm_tf32_kernel<<<gkv, 256, gemm_smem>>>(xc, wkc, kout, MROWS, NKVV * HDD, DIMM);
        gemm_tf32_kernel<<<gkv, 256, gemm_smem>>>(xc, wvc, vout, MROWS, NKVV * HDD, DIMM);
    }

    // RoPE (in place)
    {
        int totq = MROWS * NHH * 64;
        rope_kernel<<<(totq + 255) / 256, 256>>>(qptr, fc, MROWS, NHH);
        int totk = MROWS * NKVV * 64;
        rope_kernel<<<(totk + 255) / 256, 256>>>(kout, fc, MROWS, NKVV);
    }

    // Attention
    {
        size_t smem = ATTN_SMEM_FLOATS * sizeof(float);
        cudaFuncSetAttribute(attn_kernel,
                             cudaFuncAttributeMaxDynamicSharedMemorySize,
                             (int)smem);
        dim3 grid(SS / 64, NHH, BB);
        attn_kernel<<<grid, 256, smem>>>(qptr, kout, vout, ctxptr);
    }

    // Output projection
    {
        dim3 go(DIMM / 256, MROWS / 128);
        gemm_tf32_kernel<<<go, 256, gemm_smem>>>(ctxptr, woc, out, MROWS, DIMM, DIMM);
    }
}

// round 7
// speedup vs baseline: 2.2672x; 2.2672x over previous
#include <cuda_runtime.h>
#include <math.h>
#include <stdint.h>

// Problem constants
#define BB   2
#define SS   2048
#define DIMM 4096
#define NHH  32
#define NKVV 8
#define HDD  128
#define MROWS (BB*SS)            // 4096
#define OUT_ELEMS   (MROWS*DIMM) // 16777216
#define KV_ELEMS    (MROWS*NKVV*HDD) // 4194304

// Scratch (device globals -- no allocation allowed)
__device__ float g_q[(size_t)MROWS * DIMM];     // roped Q, tf32-rounded
__device__ float g_ctx[(size_t)MROWS * DIMM];   // ctx (tf32-rounded by attn epilogue)
__device__ float g_xc[(size_t)MROWS * DIMM];    // x, tf32-rounded
__device__ float g_wqc[(size_t)DIMM * DIMM];
__device__ float g_wkc[(size_t)DIMM * NKVV * HDD];
__device__ float g_wvc[(size_t)DIMM * NKVV * HDD];
__device__ float g_woc[(size_t)DIMM * DIMM];
__device__ float g_kc[(size_t)KV_ELEMS];        // roped K, tf32-rounded (attn input)
__device__ float g_vc[(size_t)KV_ELEMS];        // V, tf32-rounded (attn input)

__device__ __forceinline__ uint32_t f2tf32(float f) {
    uint32_t u;
    asm volatile("cvt.rna.tf32.f32 %0, %1;" : "=r"(u) : "f"(f));
    return u;
}

__device__ __forceinline__ void cp_async16(uint32_t dst, const void* src) {
    asm volatile("cp.async.ca.shared.global [%0], [%1], 16;\n" :: "r"(dst), "l"(src));
}
__device__ __forceinline__ void cp_commit() {
    asm volatile("cp.async.commit_group;\n");
}
template <int W>
__device__ __forceinline__ void cp_wait() {
    asm volatile("cp.async.wait_group %0;\n" :: "n"(W));
}

#define MMA_TF32(acc, a0, a1, a2, a3, b0, b1)                                  \
    asm volatile(                                                              \
        "mma.sync.aligned.m16n8k8.row.col.f32.tf32.tf32.f32 "                  \
        "{%0,%1,%2,%3}, {%4,%5,%6,%7}, {%8,%9}, {%0,%1,%2,%3};"                \
        : "+f"((acc)[0]), "+f"((acc)[1]), "+f"((acc)[2]), "+f"((acc)[3])       \
        : "r"(a0), "r"(a1), "r"(a2), "r"(a3), "r"(b0), "r"(b1))

// ----------------------------------------------------------------------------
// Elementwise tf32 rounding
// ----------------------------------------------------------------------------
__global__ void cvt_tf32_kernel(const float* __restrict__ in,
                                float* __restrict__ out, int n4)
{
    int i = blockIdx.x * blockDim.x + threadIdx.x;
    if (i >= n4) return;
    float4 v = ((const float4*)in)[i];
    float4 o;
    o.x = __uint_as_float(f2tf32(v.x));
    o.y = __uint_as_float(f2tf32(v.y));
    o.z = __uint_as_float(f2tf32(v.z));
    o.w = __uint_as_float(f2tf32(v.w));
    ((float4*)out)[i] = o;
}

// ----------------------------------------------------------------------------
// TF32 tensor-core GEMM (R3 config), 2-stage cp.async, inputs pre-rounded.
// C[M,N] = A[M,K]*B[K,N]; 128x128 tile, BK=32, 8 warps (2Mx4N), warp 64x32.
// ----------------------------------------------------------------------------
#define BK 32
#define A_STRIDE 36
#define B_STRIDE 136
#define A_STAGE (128 * A_STRIDE)
#define B_STAGE (BK * B_STRIDE)
#define GEMM_SMEM_FLOATS (2 * A_STAGE + 2 * B_STAGE)

__global__ __launch_bounds__(256) void gemm_tf32_kernel(
    const float* __restrict__ A, const float* __restrict__ Bm,
    float* __restrict__ C, int M, int N, int K)
{
    extern __shared__ float sm[];
    float* AsB = sm;
    float* BsB = sm + 2 * A_STAGE;

    const int tid   = threadIdx.x;
    const int lane  = tid & 31;
    const int warp  = tid >> 5;
    const int warpM = warp >> 2;
    const int warpN = warp & 3;
    const int bm = blockIdx.y * 128;
    const int bn = blockIdx.x * 128;

    const int qk = lane & 3;
    const int qr = lane >> 2;

    const int ntiles = K / BK;

    float acc[4][4][4];
#pragma unroll
    for (int i = 0; i < 4; i++)
#pragma unroll
        for (int j = 0; j < 4; j++)
#pragma unroll
            for (int r = 0; r < 4; r++) acc[i][j][r] = 0.0f;

    auto load_tile = [&](int t, int st) {
        const float* Asrc = A + (size_t)bm * K + t * BK;
        float* Ad = AsB + st * A_STAGE;
#pragma unroll
        for (int l = 0; l < 4; l++) {
            int flat = l * 256 + tid;
            int m  = flat >> 3;
            int kg = flat & 7;
            uint32_t dst = (uint32_t)__cvta_generic_to_shared(Ad + m * A_STRIDE + kg * 4);
            cp_async16(dst, Asrc + (size_t)m * K + kg * 4);
        }
        const float* Bsrc = Bm + (size_t)(t * BK) * N + bn;
        float* Bd = BsB + st * B_STAGE;
#pragma unroll
        for (int l = 0; l < 4; l++) {
            int flat = l * 256 + tid;
            int k  = flat >> 5;
            int ng = flat & 31;
            uint32_t dst = (uint32_t)__cvta_generic_to_shared(Bd + k * B_STRIDE + ng * 4);
            cp_async16(dst, Bsrc + (size_t)k * N + ng * 4);
        }
        cp_commit();
    };

    load_tile(0, 0);

    for (int t = 0; t < ntiles; t++) {
        const int st = t & 1;
        if (t + 1 < ntiles) {
            load_tile(t + 1, st ^ 1);
            cp_wait<1>();
        } else {
            cp_wait<0>();
        }
        __syncthreads();

        const uint32_t* As = (const uint32_t*)(AsB + st * A_STAGE);
        const uint32_t* Bs = (const uint32_t*)(BsB + st * B_STAGE);

#pragma unroll
        for (int kk = 0; kk < BK; kk += 8) {
            uint32_t af[4][4], bf[4][2];
#pragma unroll
            for (int mf = 0; mf < 4; mf++) {
                int row = warpM * 64 + mf * 16 + qr;
                af[mf][0] = As[row * A_STRIDE + kk + qk];
                af[mf][1] = As[(row + 8) * A_STRIDE + kk + qk];
                af[mf][2] = As[row * A_STRIDE + kk + qk + 4];
                af[mf][3] = As[(row + 8) * A_STRIDE + kk + qk + 4];
            }
#pragma unroll
            for (int nf = 0; nf < 4; nf++) {
                int col = warpN * 32 + nf * 8 + qr;
                bf[nf][0] = Bs[(kk + qk) * B_STRIDE + col];
                bf[nf][1] = Bs[(kk + qk + 4) * B_STRIDE + col];
            }
#pragma unroll
            for (int mf = 0; mf < 4; mf++)
#pragma unroll
                for (int nf = 0; nf < 4; nf++)
                    MMA_TF32(acc[mf][nf], af[mf][0], af[mf][1], af[mf][2], af[mf][3],
                             bf[nf][0], bf[nf][1]);
        }
        __syncthreads();
    }

#pragma unroll
    for (int mf = 0; mf < 4; mf++) {
        int row = bm + warpM * 64 + mf * 16 + qr;
#pragma unroll
        for (int nf = 0; nf < 4; nf++) {
            int col = bn + warpN * 32 + nf * 8 + 2 * qk;
            float2* p0 = (float2*)(C + (size_t)row * N + col);
            float2* p1 = (float2*)(C + (size_t)(row + 8) * N + col);
            *p0 = make_float2(acc[mf][nf][0], acc[mf][nf][1]);
            *p1 = make_float2(acc[mf][nf][2], acc[mf][nf][3]);
        }
    }
}

// ----------------------------------------------------------------------------
// RoPE, in place; optionally tf32-round the result (for Q scratch).
// ----------------------------------------------------------------------------
__global__ void rope_kernel(float* __restrict__ data,
                            const float* __restrict__ fc,
                            int rows, int heads, int round_tf32)
{
    int idx = blockIdx.x * blockDim.x + threadIdx.x;
    int total = rows * heads * 64;
    if (idx >= total) return;
    int i = idx & 63;
    int h = (idx >> 6) % heads;
    int row = idx / (heads * 64);
    int s = row & (SS - 1);
    float c = fc[(size_t)s * 128 + i * 2 + 0];
    float sn = fc[(size_t)s * 128 + i * 2 + 1];
    float* p = data + (size_t)row * heads * HDD + h * HDD + i * 2;
    float xr = p[0], xi = p[1];
    float o0 = xr * c - xi * sn;
    float o1 = xr * sn + xi * c;
    if (round_tf32) {
        o0 = __uint_as_float(f2tf32(o0));
        o1 = __uint_as_float(f2tf32(o1));
    }
    p[0] = o0;
    p[1] = o1;
}

// ----------------------------------------------------------------------------
// Tensor-core flash attention (tf32 mma), 64-query CTA, 4 warps.
// Q/K/V inputs tf32-rounded. K/V tiles (64 keys) double-buffered via cp.async.
// smem (floats): Qs[64][132] | Ks[2][64][132] | Vs[2][64][136] | P[64][72]
// ----------------------------------------------------------------------------
#define QS_OFF 0
#define KS_SZ  (64 * 132)
#define KS_OFF (64 * 132)
#define VS_SZ  (64 * 136)
#define VS_OFF (KS_OFF + 2 * KS_SZ)
#define P_OFF  (VS_OFF + 2 * VS_SZ)
#define ATT_SMEM_FLOATS (P_OFF + 64 * 72)   // 47360 floats = 189440 B

__global__ __launch_bounds__(128) void attn_mma_kernel(
    const float* __restrict__ Q, const float* __restrict__ K,
    const float* __restrict__ V, float* __restrict__ O)
{
    extern __shared__ float sm[];

    const int tid  = threadIdx.x;
    const int lane = tid & 31;
    const int warp = tid >> 5;          // 0..3
    const int qk = lane & 3;
    const int qr = lane >> 2;
    const int r0 = warp * 16 + qr;      // local q row (and r0+8)

    const int qtile = blockIdx.x;
    const int h = blockIdx.y;
    const int b = blockIdx.z;
    const int g = h >> 2;               // N_REP = 4

    const float* qbase = Q + ((size_t)b * SS + qtile * 64) * DIMM + h * HDD;
    const float* kbase = K + (size_t)b * SS * (NKVV * HDD) + g * HDD;
    const float* vbase = V + (size_t)b * SS * (NKVV * HDD) + g * HDD;

    // Q tile -> smem: 64 rows x 128 floats = 2048 float4 chunks
#pragma unroll
    for (int c = tid; c < 2048; c += 128) {
        int row = c >> 5, cc = c & 31;
        uint32_t dst = (uint32_t)__cvta_generic_to_shared(sm + QS_OFF + row * 132 + cc * 4);
        cp_async16(dst, qbase + (size_t)row * DIMM + cc * 4);
    }
    cp_commit();

    auto load_kv = [&](int t, int st) {
        const float* kb = kbase + (size_t)t * 64 * (NKVV * HDD);
        const float* vb = vbase + (size_t)t * 64 * (NKVV * HDD);
#pragma unroll
        for (int c = tid; c < 2048; c += 128) {
            int row = c >> 5, cc = c & 31;
            uint32_t dk = (uint32_t)__cvta_generic_to_shared(sm + KS_OFF + st * KS_SZ + row * 132 + cc * 4);
            cp_async16(dk, kb + (size_t)row * (NKVV * HDD) + cc * 4);
            uint32_t dv = (uint32_t)__cvta_generic_to_shared(sm + VS_OFF + st * VS_SZ + row * 136 + cc * 4);
            cp_async16(dv, vb + (size_t)row * (NKVV * HDD) + cc * 4);
        }
        cp_commit();
    };

    load_kv(0, 0);
    load_kv(1, 1);
    cp_wait<1>();       // Q + kv0 complete
    __syncthreads();

    const float scale = 0.08838834764831845f; // 1/sqrt(128)
    float m0 = -1e30f, m1 = -1e30f, l0 = 0.0f, l1 = 0.0f;
    float oacc[16][4];
#pragma unroll
    for (int nf = 0; nf < 16; nf++)
#pragma unroll
        for (int r = 0; r < 4; r++) oacc[nf][r] = 0.0f;

    const uint32_t* Qs = (const uint32_t*)(sm + QS_OFF);

    for (int t = 0; t < SS / 64; t++) {
        const int st = t & 1;
        const uint32_t* Ks = (const uint32_t*)(sm + KS_OFF + st * KS_SZ);
        const uint32_t* Vs = (const uint32_t*)(sm + VS_OFF + st * VS_SZ);
        uint32_t* P = (uint32_t*)(sm + P_OFF);

        // ---- S = Q K^T (64x64), warp computes rows [warp*16, warp*16+16) ----
        float sacc[8][4];
#pragma unroll
        for (int nf = 0; nf < 8; nf++)
#pragma unroll
            for (int r = 0; r < 4; r++) sacc[nf][r] = 0.0f;

#pragma unroll
        for (int kf = 0; kf < 16; kf++) {
            const int k0 = kf * 8;
            uint32_t a0 = Qs[r0 * 132 + k0 + qk];
            uint32_t a1 = Qs[(r0 + 8) * 132 + k0 + qk];
            uint32_t a2 = Qs[r0 * 132 + k0 + qk + 4];
            uint32_t a3 = Qs[(r0 + 8) * 132 + k0 + qk + 4];
#pragma unroll
            for (int nf = 0; nf < 8; nf++) {
                uint32_t b0 = Ks[(nf * 8 + qr) * 132 + k0 + qk];
                uint32_t b1 = Ks[(nf * 8 + qr) * 132 + k0 + qk + 4];
                MMA_TF32(sacc[nf], a0, a1, a2, a3, b0, b1);
            }
        }

        // ---- online softmax on fragments ----
        float mx0 = -1e30f, mx1 = -1e30f;
#pragma unroll
        for (int nf = 0; nf < 8; nf++) {
            mx0 = fmaxf(mx0, fmaxf(sacc[nf][0], sacc[nf][1]));
            mx1 = fmaxf(mx1, fmaxf(sacc[nf][2], sacc[nf][3]));
        }
        mx0 *= scale;
        mx1 *= scale;
        mx0 = fmaxf(mx0, __shfl_xor_sync(0xffffffffu, mx0, 1));
        mx0 = fmaxf(mx0, __shfl_xor_sync(0xffffffffu, mx0, 2));
        mx1 = fmaxf(mx1, __shfl_xor_sync(0xffffffffu, mx1, 1));
        mx1 = fmaxf(mx1, __shfl_xor_sync(0xffffffffu, mx1, 2));

        float mn0 = fmaxf(m0, mx0), mn1 = fmaxf(m1, mx1);
        float cr0 = __expf(m0 - mn0), cr1 = __expf(m1 - mn1);
        float rs0 = 0.0f, rs1 = 0.0f;
#pragma unroll
        for (int nf = 0; nf < 8; nf++) {
            float p00 = __expf(sacc[nf][0] * scale - mn0);
            float p01 = __expf(sacc[nf][1] * scale - mn0);
            float p10 = __expf(sacc[nf][2] * scale - mn1);
            float p11 = __expf(sacc[nf][3] * scale - mn1);
            rs0 += p00 + p01;
            rs1 += p10 + p11;
            uint2* q0 = (uint2*)(P + r0 * 72 + nf * 8 + 2 * qk);
            uint2* q1 = (uint2*)(P + (r0 + 8) * 72 + nf * 8 + 2 * qk);
            *q0 = make_uint2(f2tf32(p00), f2tf32(p01));
            *q1 = make_uint2(f2tf32(p10), f2tf32(p11));
        }
        rs0 += __shfl_xor_sync(0xffffffffu, rs0, 1);
        rs0 += __shfl_xor_sync(0xffffffffu, rs0, 2);
        rs1 += __shfl_xor_sync(0xffffffffu, rs1, 1);
        rs1 += __shfl_xor_sync(0xffffffffu, rs1, 2);
        l0 = l0 * cr0 + rs0;
        l1 = l1 * cr1 + rs1;
        m0 = mn0;
        m1 = mn1;
#pragma unroll
        for (int nf = 0; nf < 16; nf++) {
            oacc[nf][0] *= cr0;
            oacc[nf][1] *= cr0;
            oacc[nf][2] *= cr1;
            oacc[nf][3] *= cr1;
        }
        __syncwarp();   // P rows are private to this warp; order STS->LDS

        // ---- O += P V (P: 16x64 rows of this warp, V: 64x128) ----
#pragma unroll
        for (int kf = 0; kf < 8; kf++) {
            const int k0 = kf * 8;
            uint32_t a0 = P[r0 * 72 + k0 + qk];
            uint32_t a1 = P[(r0 + 8) * 72 + k0 + qk];
            uint32_t a2 = P[r0 * 72 + k0 + qk + 4];
            uint32_t a3 = P[(r0 + 8) * 72 + k0 + qk + 4];
#pragma unroll
            for (int nf = 0; nf < 16; nf++) {
                uint32_t b0 = Vs[(k0 + qk) * 136 + nf * 8 + qr];
                uint32_t b1 = Vs[(k0 + qk + 4) * 136 + nf * 8 + qr];
                MMA_TF32(oacc[nf], a0, a1, a2, a3, b0, b1);
            }
        }

        __syncthreads();   // everyone done reading stage st
        if (t + 2 < SS / 64) {
            load_kv(t + 2, st);
            cp_wait<1>();
        } else if (t + 1 < SS / 64) {
            cp_wait<0>();
        }
        __syncthreads();
    }

    // ---- epilogue: O / l, tf32-rounded (feeds wo GEMM) ----
    float inv0 = 1.0f / l0, inv1 = 1.0f / l1;
    float* obase = O + ((size_t)b * SS + qtile * 64) * DIMM + h * HDD;
#pragma unroll
    for (int nf = 0; nf < 16; nf++) {
        int col = nf * 8 + 2 * qk;
        uint2* p0 = (uint2*)(obase + (size_t)r0 * DIMM + col);
        uint2* p1 = (uint2*)(obase + (size_t)(r0 + 8) * DIMM + col);
        *p0 = make_uint2(f2tf32(oacc[nf][0] * inv0), f2tf32(oacc[nf][1] * inv0));
        *p1 = make_uint2(f2tf32(oacc[nf][2] * inv1), f2tf32(oacc[nf][3] * inv1));
    }
}

// ----------------------------------------------------------------------------
// Launch
// ----------------------------------------------------------------------------
extern "C" void kernel_launch(void* const* d_in, const int* in_sizes, int n_in,
                              void* d_out, int out_size)
{
    const float* x  = (const float*)d_in[0];
    const float* fc = (const float*)d_in[1];
    const float* wq = (const float*)d_in[2];
    const float* wk = (const float*)d_in[3];
    const float* wv = (const float*)d_in[4];
    const float* wo = (const float*)d_in[5];

    float* out  = (float*)d_out;
    float* kout = out + (size_t)OUT_ELEMS;
    float* vout = kout + (size_t)KV_ELEMS;

    float *qptr, *ctxptr, *xc, *wqc, *wkc, *wvc, *woc, *kc, *vc;
    cudaGetSymbolAddress((void**)&qptr, g_q);
    cudaGetSymbolAddress((void**)&ctxptr, g_ctx);
    cudaGetSymbolAddress((void**)&xc, g_xc);
    cudaGetSymbolAddress((void**)&wqc, g_wqc);
    cudaGetSymbolAddress((void**)&wkc, g_wkc);
    cudaGetSymbolAddress((void**)&wvc, g_wvc);
    cudaGetSymbolAddress((void**)&woc, g_woc);
    cudaGetSymbolAddress((void**)&kc, g_kc);
    cudaGetSymbolAddress((void**)&vc, g_vc);

    // Pre-convert GEMM operands to tf32-rounded fp32
    {
        int n4x = OUT_ELEMS / 4;
        cvt_tf32_kernel<<<(n4x + 255) / 256, 256>>>(x, xc, n4x);
        int n4w = (DIMM * DIMM) / 4;
        cvt_tf32_kernel<<<(n4w + 255) / 256, 256>>>(wq, wqc, n4w);
        cvt_tf32_kernel<<<(n4w + 255) / 256, 256>>>(wo, woc, n4w);
        int n4k = (DIMM * NKVV * HDD) / 4;
        cvt_tf32_kernel<<<(n4k + 255) / 256, 256>>>(wk, wkc, n4k);
        cvt_tf32_kernel<<<(n4k + 255) / 256, 256>>>(wv, wvc, n4k);
    }

    size_t gemm_smem = GEMM_SMEM_FLOATS * sizeof(float); // 71680 B
    cudaFuncSetAttribute(gemm_tf32_kernel,
                         cudaFuncAttributeMaxDynamicSharedMemorySize,
                         (int)gemm_smem);

    // Projections
    {
        dim3 gq(DIMM / 128, MROWS / 128);
        gemm_tf32_kernel<<<gq, 256, gemm_smem>>>(xc, wqc, qptr, MROWS, DIMM, DIMM);
        dim3 gkv((NKVV * HDD) / 128, MROWS / 128);
        gemm_tf32_kernel<<<gkv, 256, gemm_smem>>>(xc, wkc, kout, MROWS, NKVV * HDD, DIMM);
        gemm_tf32_kernel<<<gkv, 256, gemm_smem>>>(xc, wvc, vout, MROWS, NKVV * HDD, DIMM);
    }

    // RoPE: Q (rounded, scratch) and K (exact, output buffer)
    {
        int totq = MROWS * NHH * 64;
        rope_kernel<<<(totq + 255) / 256, 256>>>(qptr, fc, MROWS, NHH, 1);
        int totk = MROWS * NKVV * 64;
        rope_kernel<<<(totk + 255) / 256, 256>>>(kout, fc, MROWS, NKVV, 0);
    }

    // tf32-rounded copies of roped K and V for the attention mma
    {
        int n4 = KV_ELEMS / 4;
        cvt_tf32_kernel<<<(n4 + 255) / 256, 256>>>(kout, kc, n4);
        cvt_tf32_kernel<<<(n4 + 255) / 256, 256>>>(vout, vc, n4);
    }

    // Attention (tensor cores)
    {
        size_t smem = ATT_SMEM_FLOATS * sizeof(float); // 189440 B
        cudaFuncSetAttribute(attn_mma_kernel,
                             cudaFuncAttributeMaxDynamicSharedMemorySize,
                             (int)smem);
        dim3 grid(SS / 64, NHH, BB);
        attn_mma_kernel<<<grid, 128, smem>>>(qptr, kc, vc, ctxptr);
    }

    // Output projection
    {
        dim3 go(DIMM / 128, MROWS / 128);
        gemm_tf32_kernel<<<go, 256, gemm_smem>>>(ctxptr, woc, out, MROWS, DIMM, DIMM);
    }
}

// round 9
// speedup vs baseline: 2.4917x; 1.0990x over previous
#include <cuda_runtime.h>
#include <math.h>
#include <stdint.h>

// Problem constants
#define BB   2
#define SS   2048
#define DIMM 4096
#define NHH  32
#define NKVV 8
#define HDD  128
#define MROWS (BB*SS)            // 4096
#define OUT_ELEMS   (MROWS*DIMM) // 16777216
#define KV_ELEMS    (MROWS*NKVV*HDD) // 4194304
#define NQKV (DIMM + 2 * NKVV * HDD)  // 6144 merged projection width

// Scratch (device globals -- no allocation allowed)
__device__ float g_q[(size_t)MROWS * DIMM];     // roped Q, tf32-rounded
__device__ float g_ctx[(size_t)MROWS * DIMM];   // ctx (tf32-rounded by attn epilogue)
__device__ float g_xc[(size_t)MROWS * DIMM];    // x, tf32-rounded
__device__ float g_wqkv[(size_t)DIMM * NQKV];   // [wq|wk|wv] packed, tf32-rounded
__device__ float g_woc[(size_t)DIMM * DIMM];    // wo, tf32-rounded
__device__ float g_kc[(size_t)KV_ELEMS];        // roped K, tf32-rounded (attn input)
__device__ float g_vc[(size_t)KV_ELEMS];        // V, tf32-rounded (attn input)

__device__ __forceinline__ uint32_t f2tf32(float f) {
    uint32_t u;
    asm volatile("cvt.rna.tf32.f32 %0, %1;" : "=r"(u) : "f"(f));
    return u;
}

__device__ __forceinline__ void cp_async16(uint32_t dst, const void* src) {
    asm volatile("cp.async.ca.shared.global [%0], [%1], 16;\n" :: "r"(dst), "l"(src));
}
__device__ __forceinline__ void cp_commit() {
    asm volatile("cp.async.commit_group;\n");
}
template <int W>
__device__ __forceinline__ void cp_wait() {
    asm volatile("cp.async.wait_group %0;\n" :: "n"(W));
}

#define MMA_TF32(acc, a0, a1, a2, a3, b0, b1)                                  \
    asm volatile(                                                              \
        "mma.sync.aligned.m16n8k8.row.col.f32.tf32.tf32.f32 "                  \
        "{%0,%1,%2,%3}, {%4,%5,%6,%7}, {%8,%9}, {%0,%1,%2,%3};"                \
        : "+f"((acc)[0]), "+f"((acc)[1]), "+f"((acc)[2]), "+f"((acc)[3])       \
        : "r"(a0), "r"(a1), "r"(a2), "r"(a3), "r"(b0), "r"(b1))

// ----------------------------------------------------------------------------
// Elementwise tf32 rounding
// ----------------------------------------------------------------------------
__global__ void cvt_tf32_kernel(const float* __restrict__ in,
                                float* __restrict__ out, int n4)
{
    int i = blockIdx.x * blockDim.x + threadIdx.x;
    if (i >= n4) return;
    float4 v = ((const float4*)in)[i];
    float4 o;
    o.x = __uint_as_float(f2tf32(v.x));
    o.y = __uint_as_float(f2tf32(v.y));
    o.z = __uint_as_float(f2tf32(v.z));
    o.w = __uint_as_float(f2tf32(v.w));
    ((float4*)out)[i] = o;
}

// ----------------------------------------------------------------------------
// tf32 round + place segment: in [K][Nin] -> out[k*ldo + coff + n]
// ----------------------------------------------------------------------------
__global__ void cvt_seg_kernel(const float* __restrict__ in,
                               float* __restrict__ out,
                               int K, int Nin, int ldo, int coff)
{
    int i = blockIdx.x * blockDim.x + threadIdx.x;
    int n4 = Nin >> 2;
    if (i >= K * n4) return;
    int row = i / n4, c4 = i - row * n4;
    float4 v = ((const float4*)(in + (size_t)row * Nin))[c4];
    float4 o;
    o.x = __uint_as_float(f2tf32(v.x));
    o.y = __uint_as_float(f2tf32(v.y));
    o.z = __uint_as_float(f2tf32(v.z));
    o.w = __uint_as_float(f2tf32(v.w));
    ((float4*)(out + (size_t)row * ldo + coff))[c4] = o;
}

// ----------------------------------------------------------------------------
// TF32 tensor-core GEMM (mma.sync, R7-proven config) with split epilogue.
// C = A[M,K] * Bm[K,N]; 128x128 tile, BK=32, 8 warps (2Mx4N), warp 64x32.
// Output column ranges: [0,split1)->C0/ld0, [split1,split2)->C1/ld1, rest->C2/ld2.
// ----------------------------------------------------------------------------
#define BK 32
#define A_STRIDE 36
#define B_STRIDE 136
#define A_STAGE (128 * A_STRIDE)
#define B_STAGE (BK * B_STRIDE)
#define GEMM_SMEM_FLOATS (2 * A_STAGE + 2 * B_STAGE)

__global__ __launch_bounds__(256) void gemm_tf32_kernel(
    const float* __restrict__ A, const float* __restrict__ Bm,
    float* __restrict__ C0, int ld0, int split1,
    float* __restrict__ C1, int ld1, int split2,
    float* __restrict__ C2, int ld2,
    int M, int N, int K)
{
    extern __shared__ float sm[];
    float* AsB = sm;
    float* BsB = sm + 2 * A_STAGE;

    const int tid   = threadIdx.x;
    const int lane  = tid & 31;
    const int warp  = tid >> 5;
    const int warpM = warp >> 2;
    const int warpN = warp & 3;
    const int bm = blockIdx.y * 128;
    const int bn = blockIdx.x * 128;

    const int qk = lane & 3;
    const int qr = lane >> 2;

    const int ntiles = K / BK;

    float acc[4][4][4];
#pragma unroll
    for (int i = 0; i < 4; i++)
#pragma unroll
        for (int j = 0; j < 4; j++)
#pragma unroll
            for (int r = 0; r < 4; r++) acc[i][j][r] = 0.0f;

    auto load_tile = [&](int t, int st) {
        const float* Asrc = A + (size_t)bm * K + t * BK;
        float* Ad = AsB + st * A_STAGE;
#pragma unroll
        for (int l = 0; l < 4; l++) {
            int flat = l * 256 + tid;
            int m  = flat >> 3;
            int kg = flat & 7;
            uint32_t dst = (uint32_t)__cvta_generic_to_shared(Ad + m * A_STRIDE + kg * 4);
            cp_async16(dst, Asrc + (size_t)m * K + kg * 4);
        }
        const float* Bsrc = Bm + (size_t)(t * BK) * N + bn;
        float* Bd = BsB + st * B_STAGE;
#pragma unroll
        for (int l = 0; l < 4; l++) {
            int flat = l * 256 + tid;
            int k  = flat >> 5;
            int ng = flat & 31;
            uint32_t dst = (uint32_t)__cvta_generic_to_shared(Bd + k * B_STRIDE + ng * 4);
            cp_async16(dst, Bsrc + (size_t)k * N + ng * 4);
        }
        cp_commit();
    };

    load_tile(0, 0);

    for (int t = 0; t < ntiles; t++) {
        const int st = t & 1;
        if (t + 1 < ntiles) {
            load_tile(t + 1, st ^ 1);
            cp_wait<1>();
        } else {
            cp_wait<0>();
        }
        __syncthreads();

        const uint32_t* As = (const uint32_t*)(AsB + st * A_STAGE);
        const uint32_t* Bs = (const uint32_t*)(BsB + st * B_STAGE);

#pragma unroll
        for (int kk = 0; kk < BK; kk += 8) {
            uint32_t af[4][4], bf[4][2];
#pragma unroll
            for (int mf = 0; mf < 4; mf++) {
                int row = warpM * 64 + mf * 16 + qr;
                af[mf][0] = As[row * A_STRIDE + kk + qk];
                af[mf][1] = As[(row + 8) * A_STRIDE + kk + qk];
                af[mf][2] = As[row * A_STRIDE + kk + qk + 4];
                af[mf][3] = As[(row + 8) * A_STRIDE + kk + qk + 4];
            }
#pragma unroll
            for (int nf = 0; nf < 4; nf++) {
                int col = warpN * 32 + nf * 8 + qr;
                bf[nf][0] = Bs[(kk + qk) * B_STRIDE + col];
                bf[nf][1] = Bs[(kk + qk + 4) * B_STRIDE + col];
            }
#pragma unroll
            for (int mf = 0; mf < 4; mf++)
#pragma unroll
                for (int nf = 0; nf < 4; nf++)
                    MMA_TF32(acc[mf][nf], af[mf][0], af[mf][1], af[mf][2], af[mf][3],
                             bf[nf][0], bf[nf][1]);
        }
        __syncthreads();
    }

    // split epilogue (CTA-uniform segment: 128-wide tiles never cross splits)
    float* Cb;
    int ld, coff;
    if (bn < split1)      { Cb = C0; ld = ld0; coff = bn; }
    else if (bn < split2) { Cb = C1; ld = ld1; coff = bn - split1; }
    else                  { Cb = C2; ld = ld2; coff = bn - split2; }

#pragma unroll
    for (int mf = 0; mf < 4; mf++) {
        int row = bm + warpM * 64 + mf * 16 + qr;
#pragma unroll
        for (int nf = 0; nf < 4; nf++) {
            int col = coff + warpN * 32 + nf * 8 + 2 * qk;
            float2* p0 = (float2*)(Cb + (size_t)row * ld + col);
            float2* p1 = (float2*)(Cb + (size_t)(row + 8) * ld + col);
            *p0 = make_float2(acc[mf][nf][0], acc[mf][nf][1]);
            *p1 = make_float2(acc[mf][nf][2], acc[mf][nf][3]);
        }
    }
}

// ----------------------------------------------------------------------------
// RoPE. If round_inplace: data gets tf32-rounded result. If rout != null:
// rout gets the tf32-rounded result (data keeps exact).
// ----------------------------------------------------------------------------
__global__ void rope_kernel(float* __restrict__ data,
                            float* __restrict__ rout,
                            const float* __restrict__ fc,
                            int rows, int heads, int round_inplace)
{
    int idx = blockIdx.x * blockDim.x + threadIdx.x;
    int total = rows * heads * 64;
    if (idx >= total) return;
    int i = idx & 63;
    int h = (idx >> 6) % heads;
    int row = idx / (heads * 64);
    int s = row & (SS - 1);
    float c = fc[(size_t)s * 128 + i * 2 + 0];
    float sn = fc[(size_t)s * 128 + i * 2 + 1];
    size_t off = (size_t)row * heads * HDD + h * HDD + i * 2;
    float* p = data + off;
    float xr = p[0], xi = p[1];
    float o0 = xr * c - xi * sn;
    float o1 = xr * sn + xi * c;
    float r0 = __uint_as_float(f2tf32(o0));
    float r1 = __uint_as_float(f2tf32(o1));
    if (round_inplace) {
        p[0] = r0;
        p[1] = r1;
    } else {
        p[0] = o0;
        p[1] = o1;
    }
    if (rout) {
        rout[off]     = r0;
        rout[off + 1] = r1;
    }
}

// ----------------------------------------------------------------------------
// Tensor-core flash attention (tf32 mma.sync), GQA-shared K/V.
// CTA = 64 A-rows = 4 heads x 16 queries; warp w owns head g*4+w, 16 queries.
// grid: (SS/16, NKVV, BB). K/V tiles loaded ONCE per 4 heads.
// smem (floats): Qs[64][132] | Ks[2][64][132] | Vs[2][64][136] | P[64][72]
// ----------------------------------------------------------------------------
#define QS_OFF 0
#define KS_SZ  (64 * 132)
#define KS_OFF (64 * 132)
#define VS_SZ  (64 * 136)
#define VS_OFF (KS_OFF + 2 * KS_SZ)
#define P_OFF  (VS_OFF + 2 * VS_SZ)
#define ATT_SMEM_FLOATS (P_OFF + 64 * 72)   // 47360 floats = 189440 B

__global__ __launch_bounds__(128) void attn_mma_kernel(
    const float* __restrict__ Q, const float* __restrict__ K,
    const float* __restrict__ V, float* __restrict__ O)
{
    extern __shared__ float sm[];

    const int tid  = threadIdx.x;
    const int lane = tid & 31;
    const int warp = tid >> 5;          // 0..3 == head_local
    const int qk = lane & 3;
    const int qr = lane >> 2;
    const int r0 = warp * 16 + qr;      // local A row (and r0+8)

    const int qt16 = blockIdx.x;        // 16-query tile
    const int g = blockIdx.y;           // kv group
    const int b = blockIdx.z;

    const float* kbase = K + (size_t)b * SS * (NKVV * HDD) + g * HDD;
    const float* vbase = V + (size_t)b * SS * (NKVV * HDD) + g * HDD;

    // Q tile: local row r -> head g*4 + (r>>4), query qt16*16 + (r&15)
#pragma unroll
    for (int c = tid; c < 2048; c += 128) {
        int row = c >> 5, cc = c & 31;
        const float* src = Q + ((size_t)b * SS + qt16 * 16 + (row & 15)) * DIMM
                             + (g * 4 + (row >> 4)) * HDD + cc * 4;
        uint32_t dst = (uint32_t)__cvta_generic_to_shared(sm + QS_OFF + row * 132 + cc * 4);
        cp_async16(dst, src);
    }
    cp_commit();

    auto load_kv = [&](int t, int st) {
        const float* kb = kbase + (size_t)t * 64 * (NKVV * HDD);
        const float* vb = vbase + (size_t)t * 64 * (NKVV * HDD);
#pragma unroll
        for (int c = tid; c < 2048; c += 128) {
            int row = c >> 5, cc = c & 31;
            uint32_t dk = (uint32_t)__cvta_generic_to_shared(sm + KS_OFF + st * KS_SZ + row * 132 + cc * 4);
            cp_async16(dk, kb + (size_t)row * (NKVV * HDD) + cc * 4);
            uint32_t dv = (uint32_t)__cvta_generic_to_shared(sm + VS_OFF + st * VS_SZ + row * 136 + cc * 4);
            cp_async16(dv, vb + (size_t)row * (NKVV * HDD) + cc * 4);
        }
        cp_commit();
    };

    load_kv(0, 0);
    load_kv(1, 1);
    cp_wait<1>();
    __syncthreads();

    const float scale = 0.08838834764831845f;
    float m0 = -1e30f, m1 = -1e30f, l0 = 0.0f, l1 = 0.0f;
    float oacc[16][4];
#pragma unroll
    for (int nf = 0; nf < 16; nf++)
#pragma unroll
        for (int r = 0; r < 4; r++) oacc[nf][r] = 0.0f;

    const uint32_t* Qs = (const uint32_t*)(sm + QS_OFF);

    for (int t = 0; t < SS / 64; t++) {
        const int st = t & 1;
        const uint32_t* Ks = (const uint32_t*)(sm + KS_OFF + st * KS_SZ);
        const uint32_t* Vs = (const uint32_t*)(sm + VS_OFF + st * VS_SZ);
        uint32_t* P = (uint32_t*)(sm + P_OFF);

        float sacc[8][4];
#pragma unroll
        for (int nf = 0; nf < 8; nf++)
#pragma unroll
            for (int r = 0; r < 4; r++) sacc[nf][r] = 0.0f;

#pragma unroll
        for (int kf = 0; kf < 16; kf++) {
            const int k0 = kf * 8;
            uint32_t a0 = Qs[r0 * 132 + k0 + qk];
            uint32_t a1 = Qs[(r0 + 8) * 132 + k0 + qk];
            uint32_t a2 = Qs[r0 * 132 + k0 + qk + 4];
            uint32_t a3 = Qs[(r0 + 8) * 132 + k0 + qk + 4];
#pragma unroll
            for (int nf = 0; nf < 8; nf++) {
                uint32_t b0 = Ks[(nf * 8 + qr) * 132 + k0 + qk];
                uint32_t b1 = Ks[(nf * 8 + qr) * 132 + k0 + qk + 4];
                MMA_TF32(sacc[nf], a0, a1, a2, a3, b0, b1);
            }
        }

        float mx0 = -1e30f, mx1 = -1e30f;
#pragma unroll
        for (int nf = 0; nf < 8; nf++) {
            mx0 = fmaxf(mx0, fmaxf(sacc[nf][0], sacc[nf][1]));
            mx1 = fmaxf(mx1, fmaxf(sacc[nf][2], sacc[nf][3]));
        }
        mx0 *= scale;
        mx1 *= scale;
        mx0 = fmaxf(mx0, __shfl_xor_sync(0xffffffffu, mx0, 1));
        mx0 = fmaxf(mx0, __shfl_xor_sync(0xffffffffu, mx0, 2));
        mx1 = fmaxf(mx1, __shfl_xor_sync(0xffffffffu, mx1, 1));
        mx1 = fmaxf(mx1, __shfl_xor_sync(0xffffffffu, mx1, 2));

        float mn0 = fmaxf(m0, mx0), mn1 = fmaxf(m1, mx1);
        float cr0 = __expf(m0 - mn0), cr1 = __expf(m1 - mn1);
        float rs0 = 0.0f, rs1 = 0.0f;
#pragma unroll
        for (int nf = 0; nf < 8; nf++) {
            float p00 = __expf(sacc[nf][0] * scale - mn0);
            float p01 = __expf(sacc[nf][1] * scale - mn0);
            float p10 = __expf(sacc[nf][2] * scale - mn1);
            float p11 = __expf(sacc[nf][3] * scale - mn1);
            rs0 += p00 + p01;
            rs1 += p10 + p11;
            uint2* q0 = (uint2*)(P + r0 * 72 + nf * 8 + 2 * qk);
            uint2* q1 = (uint2*)(P + (r0 + 8) * 72 + nf * 8 + 2 * qk);
            *q0 = make_uint2(f2tf32(p00), f2tf32(p01));
            *q1 = make_uint2(f2tf32(p10), f2tf32(p11));
        }
        rs0 += __shfl_xor_sync(0xffffffffu, rs0, 1);
        rs0 += __shfl_xor_sync(0xffffffffu, rs0, 2);
        rs1 += __shfl_xor_sync(0xffffffffu, rs1, 1);
        rs1 += __shfl_xor_sync(0xffffffffu, rs1, 2);
        l0 = l0 * cr0 + rs0;
        l1 = l1 * cr1 + rs1;
        m0 = mn0;
        m1 = mn1;
#pragma unroll
        for (int nf = 0; nf < 16; nf++) {
            oacc[nf][0] *= cr0;
            oacc[nf][1] *= cr0;
            oacc[nf][2] *= cr1;
            oacc[nf][3] *= cr1;
        }
        __syncwarp();

#pragma unroll
        for (int kf = 0; kf < 8; kf++) {
            const int k0 = kf * 8;
            uint32_t a0 = P[r0 * 72 + k0 + qk];
            uint32_t a1 = P[(r0 + 8) * 72 + k0 + qk];
            uint32_t a2 = P[r0 * 72 + k0 + qk + 4];
            uint32_t a3 = P[(r0 + 8) * 72 + k0 + qk + 4];
#pragma unroll
            for (int nf = 0; nf < 16; nf++) {
                uint32_t b0 = Vs[(k0 + qk) * 136 + nf * 8 + qr];
                uint32_t b1 = Vs[(k0 + qk + 4) * 136 + nf * 8 + qr];
                MMA_TF32(oacc[nf], a0, a1, a2, a3, b0, b1);
            }
        }

        __syncthreads();
        if (t + 2 < SS / 64) {
            load_kv(t + 2, st);
            cp_wait<1>();
        } else if (t + 1 < SS / 64) {
            cp_wait<0>();
        }
        __syncthreads();
    }

    // epilogue: warp w -> head g*4+w, queries qt16*16 + qr and +8
    float inv0 = 1.0f / l0, inv1 = 1.0f / l1;
    float* obase = O + ((size_t)b * SS + qt16 * 16) * DIMM + (g * 4 + warp) * HDD;
#pragma unroll
    for (int nf = 0; nf < 16; nf++) {
        int col = nf * 8 + 2 * qk;
        uint2* p0 = (uint2*)(obase + (size_t)qr * DIMM + col);
        uint2* p1 = (uint2*)(obase + (size_t)(qr + 8) * DIMM + col);
        *p0 = make_uint2(f2tf32(oacc[nf][0] * inv0), f2tf32(oacc[nf][1] * inv0));
        *p1 = make_uint2(f2tf32(oacc[nf][2] * inv1), f2tf32(oacc[nf][3] * inv1));
    }
}

// ----------------------------------------------------------------------------
// Launch
// ----------------------------------------------------------------------------
extern "C" void kernel_launch(void* const* d_in, const int* in_sizes, int n_in,
                              void* d_out, int out_size)
{
    const float* x  = (const float*)d_in[0];
    const float* fc = (const float*)d_in[1];
    const float* wq = (const float*)d_in[2];
    const float* wk = (const float*)d_in[3];
    const float* wv = (const float*)d_in[4];
    const float* wo = (const float*)d_in[5];

    float* out  = (float*)d_out;
    float* kout = out + (size_t)OUT_ELEMS;
    float* vout = kout + (size_t)KV_ELEMS;

    float *qptr, *ctxptr, *xc, *wqkv, *woc, *kc, *vc;
    cudaGetSymbolAddress((void**)&qptr, g_q);
    cudaGetSymbolAddress((void**)&ctxptr, g_ctx);
    cudaGetSymbolAddress((void**)&xc, g_xc);
    cudaGetSymbolAddress((void**)&wqkv, g_wqkv);
    cudaGetSymbolAddress((void**)&woc, g_woc);
    cudaGetSymbolAddress((void**)&kc, g_kc);
    cudaGetSymbolAddress((void**)&vc, g_vc);

    // tf32 rounding passes: x, packed [wq|wk|wv], wo
    {
        int n4x = OUT_ELEMS / 4;
        cvt_tf32_kernel<<<(n4x + 255) / 256, 256>>>(x, xc, n4x);
        int nq = DIMM * DIMM / 4;
        cvt_seg_kernel<<<(nq + 255) / 256, 256>>>(wq, wqkv, DIMM, DIMM, NQKV, 0);
        int nk = DIMM * (NKVV * HDD) / 4;
        cvt_seg_kernel<<<(nk + 255) / 256, 256>>>(wk, wqkv, DIMM, NKVV * HDD, NQKV, DIMM);
        cvt_seg_kernel<<<(nk + 255) / 256, 256>>>(wv, wqkv, DIMM, NKVV * HDD, NQKV, DIMM + NKVV * HDD);
        cvt_seg_kernel<<<(nq + 255) / 256, 256>>>(wo, woc, DIMM, DIMM, DIMM, 0);
    }

    size_t gemm_smem = GEMM_SMEM_FLOATS * sizeof(float); // 71680 B
    cudaFuncSetAttribute(gemm_tf32_kernel,
                         cudaFuncAttributeMaxDynamicSharedMemorySize,
                         (int)gemm_smem);

    // Merged Q/K/V projection: one GEMM, split epilogue
    {
        dim3 gg(NQKV / 128, MROWS / 128);   // 48 x 32
        gemm_tf32_kernel<<<gg, 256, gemm_smem>>>(
            xc, wqkv,
            qptr, DIMM, DIMM,
            kout, NKVV * HDD, DIMM + NKVV * HDD,
            vout, NKVV * HDD,
            MROWS, NQKV, DIMM);
    }

    // RoPE: Q rounded in place; K exact in place + rounded copy to kc
    {
        int totq = MROWS * NHH * 64;
        rope_kernel<<<(totq + 255) / 256, 256>>>(qptr, nullptr, fc, MROWS, NHH, 1);
        int totk = MROWS * NKVV * 64;
        rope_kernel<<<(totk + 255) / 256, 256>>>(kout, kc, fc, MROWS, NKVV, 0);
    }

    // Rounded V copy for attention
    {
        int n4 = KV_ELEMS / 4;
        cvt_tf32_kernel<<<(n4 + 255) / 256, 256>>>(vout, vc, n4);
    }

    // Attention (mma.sync flash, GQA-shared K/V)
    {
        size_t smem = ATT_SMEM_FLOATS * sizeof(float);
        cudaFuncSetAttribute(attn_mma_kernel,
                             cudaFuncAttributeMaxDynamicSharedMemorySize, (int)smem);
        dim3 grid(SS / 16, NKVV, BB);
        attn_mma_kernel<<<grid, 128, smem>>>(qptr, kc, vc, ctxptr);
    }

    // Output projection
    {
        dim3 go(DIMM / 128, MROWS / 128);
        gemm_tf32_kernel<<<go, 256, gemm_smem>>>(
            ctxptr, woc,
            out, DIMM, DIMM,
            nullptr, 0, DIMM,
            nullptr, 0,
            MROWS, DIMM, DIMM);
    }
}

// round 10
// speedup vs baseline: 3.5438x; 1.4222x over previous
#include <cuda_runtime.h>
#include <cuda_fp16.h>
#include <math.h>
#include <stdint.h>

// Problem constants
#define BB   2
#define SS   2048
#define DIMM 4096
#define NHH  32
#define NKVV 8
#define HDD  128
#define MROWS (BB*SS)            // 4096
#define OUT_ELEMS   (MROWS*DIMM) // 16777216
#define KV_ELEMS    (MROWS*NKVV*HDD) // 4194304
#define NQKV (DIMM + 2 * NKVV * HDD)  // 6144 merged projection width

// Scratch (device globals -- no allocation allowed)
__device__ float  g_q[(size_t)MROWS * DIMM];      // roped Q, tf32-rounded
__device__ __half g_ctxh[(size_t)MROWS * DIMM];   // ctx (half, from attn epilogue)
__device__ __half g_xh[(size_t)MROWS * DIMM];     // x, half
__device__ __half g_wqkvh[(size_t)NQKV * DIMM];   // [wq|wk|wv]^T packed, [N][K] half
__device__ __half g_woh[(size_t)DIMM * DIMM];     // wo^T, [N][K] half
__device__ float  g_kc[(size_t)KV_ELEMS];         // roped K, tf32-rounded (attn)
__device__ float  g_vc[(size_t)KV_ELEMS];         // V, tf32-rounded (attn)

__device__ __forceinline__ uint32_t f2tf32(float f) {
    uint32_t u;
    asm volatile("cvt.rna.tf32.f32 %0, %1;" : "=r"(u) : "f"(f));
    return u;
}

__device__ __forceinline__ void cp_async16(uint32_t dst, const void* src) {
    asm volatile("cp.async.ca.shared.global [%0], [%1], 16;\n" :: "r"(dst), "l"(src));
}
__device__ __forceinline__ void cp_commit() {
    asm volatile("cp.async.commit_group;\n");
}
template <int W>
__device__ __forceinline__ void cp_wait() {
    asm volatile("cp.async.wait_group %0;\n" :: "n"(W));
}

#define MMA_TF32(acc, a0, a1, a2, a3, b0, b1)                                  \
    asm volatile(                                                              \
        "mma.sync.aligned.m16n8k8.row.col.f32.tf32.tf32.f32 "                  \
        "{%0,%1,%2,%3}, {%4,%5,%6,%7}, {%8,%9}, {%0,%1,%2,%3};"                \
        : "+f"((acc)[0]), "+f"((acc)[1]), "+f"((acc)[2]), "+f"((acc)[3])       \
        : "r"(a0), "r"(a1), "r"(a2), "r"(a3), "r"(b0), "r"(b1))

#define MMA_F16(acc, a0, a1, a2, a3, b0, b1)                                   \
    asm volatile(                                                              \
        "mma.sync.aligned.m16n8k16.row.col.f32.f16.f16.f32 "                   \
        "{%0,%1,%2,%3}, {%4,%5,%6,%7}, {%8,%9}, {%0,%1,%2,%3};"                \
        : "+f"((acc)[0]), "+f"((acc)[1]), "+f"((acc)[2]), "+f"((acc)[3])       \
        : "r"(a0), "r"(a1), "r"(a2), "r"(a3), "r"(b0), "r"(b1))

// ----------------------------------------------------------------------------
// Elementwise conversions
// ----------------------------------------------------------------------------
__global__ void cvt_tf32_kernel(const float* __restrict__ in,
                                float* __restrict__ out, int n4)
{
    int i = blockIdx.x * blockDim.x + threadIdx.x;
    if (i >= n4) return;
    float4 v = ((const float4*)in)[i];
    float4 o;
    o.x = __uint_as_float(f2tf32(v.x));
    o.y = __uint_as_float(f2tf32(v.y));
    o.z = __uint_as_float(f2tf32(v.z));
    o.w = __uint_as_float(f2tf32(v.w));
    ((float4*)out)[i] = o;
}

__global__ void cvt_half_kernel(const float* __restrict__ in,
                                __half* __restrict__ out, int n4)
{
    int i = blockIdx.x * blockDim.x + threadIdx.x;
    if (i >= n4) return;
    float4 v = ((const float4*)in)[i];
    __half2 h0 = __floats2half2_rn(v.x, v.y);
    __half2 h1 = __floats2half2_rn(v.z, v.w);
    ((__half2*)out)[i * 2]     = h0;
    ((__half2*)out)[i * 2 + 1] = h1;
}

// ----------------------------------------------------------------------------
// Transpose + half convert: in [K][Nin] fp32 -> out[(coff+n)][K] half
// block (32,8), grid (Nin/32, K/32)
// ----------------------------------------------------------------------------
__global__ void transpose_cvt_h_kernel(const float* __restrict__ in,
                                       __half* __restrict__ out,
                                       int K, int Nin, int coff)
{
    __shared__ float tile[32][33];
    int x = blockIdx.x * 32 + threadIdx.x;   // N index
    int y0 = blockIdx.y * 32;                // K base
#pragma unroll
    for (int i = threadIdx.y; i < 32; i += 8)
        tile[i][threadIdx.x] = in[(size_t)(y0 + i) * Nin + x];
    __syncthreads();
    int xo = y0 + threadIdx.x;               // K index in out
    int yo0 = coff + blockIdx.x * 32;        // N base in out
#pragma unroll
    for (int i = threadIdx.y; i < 32; i += 8)
        out[(size_t)(yo0 + i) * K + xo] = __float2half_rn(tile[threadIdx.x][i]);
}

// ----------------------------------------------------------------------------
// FP16 tensor-core GEMM with split epilogue.
// C = A[M,K] * BT[N,K]^T (A,BT half; C fp32).
// 128x128 tile, BK=64 halves, 8 warps (2Mx4N), warp 64x32, m16n8k16.
// smem: A/B tiles [128][72] halves (stride 72 -> conflict-free 32b frag LDS).
// ----------------------------------------------------------------------------
#define BKH 64
#define STRH 72                       // halves per row (36 words)
#define STAGE_H (128 * STRH)          // halves per matrix per stage
#define GEMM_SMEM_BYTES (4 * STAGE_H * 2)   // 2 stages x (A+B) x 2B = 73728

__global__ __launch_bounds__(256) void gemm_f16_kernel(
    const __half* __restrict__ A, const __half* __restrict__ BT,
    float* __restrict__ C0, int ld0, int split1,
    float* __restrict__ C1, int ld1, int split2,
    float* __restrict__ C2, int ld2,
    int M, int N, int K)
{
    extern __shared__ __half smh[];
    __half* AsB = smh;                       // [2][STAGE_H]
    __half* BsB = smh + 2 * STAGE_H;

    const int tid   = threadIdx.x;
    const int lane  = tid & 31;
    const int warp  = tid >> 5;
    const int warpM = warp >> 2;
    const int warpN = warp & 3;
    const int bm = blockIdx.y * 128;
    const int bn = blockIdx.x * 128;

    const int qk = lane & 3;
    const int qr = lane >> 2;

    const int ntiles = K / BKH;

    float acc[4][4][4];
#pragma unroll
    for (int i = 0; i < 4; i++)
#pragma unroll
        for (int j = 0; j < 4; j++)
#pragma unroll
            for (int r = 0; r < 4; r++) acc[i][j][r] = 0.0f;

    auto load_tile = [&](int t, int st) {
        const __half* Asrc = A + (size_t)bm * K + t * BKH;
        __half* Ad = AsB + st * STAGE_H;
#pragma unroll
        for (int l = 0; l < 4; l++) {
            int flat = l * 256 + tid;        // 0..1023
            int row = flat >> 3;             // 0..127
            int cg  = flat & 7;              // 8 chunks of 8 halves
            uint32_t dst = (uint32_t)__cvta_generic_to_shared(Ad + row * STRH + cg * 8);
            cp_async16(dst, Asrc + (size_t)row * K + cg * 8);
        }
        const __half* Bsrc = BT + (size_t)bn * K + t * BKH;
        __half* Bd = BsB + st * STAGE_H;
#pragma unroll
        for (int l = 0; l < 4; l++) {
            int flat = l * 256 + tid;
            int row = flat >> 3;
            int cg  = flat & 7;
            uint32_t dst = (uint32_t)__cvta_generic_to_shared(Bd + row * STRH + cg * 8);
            cp_async16(dst, Bsrc + (size_t)row * K + cg * 8);
        }
        cp_commit();
    };

    load_tile(0, 0);

    for (int t = 0; t < ntiles; t++) {
        const int st = t & 1;
        if (t + 1 < ntiles) {
            load_tile(t + 1, st ^ 1);
            cp_wait<1>();
        } else {
            cp_wait<0>();
        }
        __syncthreads();

        const uint32_t* As = (const uint32_t*)(AsB + st * STAGE_H);
        const uint32_t* Bs = (const uint32_t*)(BsB + st * STAGE_H);

#pragma unroll
        for (int kk2 = 0; kk2 < 32; kk2 += 8) {   // 4 k-steps of 16 halves
            uint32_t af[4][4], bf[4][2];
#pragma unroll
            for (int mf = 0; mf < 4; mf++) {
                int row = warpM * 64 + mf * 16 + qr;
                af[mf][0] = As[row * 36 + kk2 + qk];
                af[mf][1] = As[(row + 8) * 36 + kk2 + qk];
                af[mf][2] = As[row * 36 + kk2 + qk + 4];
                af[mf][3] = As[(row + 8) * 36 + kk2 + qk + 4];
            }
#pragma unroll
            for (int nf = 0; nf < 4; nf++) {
                int col = warpN * 32 + nf * 8 + qr;
                bf[nf][0] = Bs[col * 36 + kk2 + qk];
                bf[nf][1] = Bs[col * 36 + kk2 + qk + 4];
            }
#pragma unroll
            for (int mf = 0; mf < 4; mf++)
#pragma unroll
                for (int nf = 0; nf < 4; nf++)
                    MMA_F16(acc[mf][nf], af[mf][0], af[mf][1], af[mf][2], af[mf][3],
                            bf[nf][0], bf[nf][1]);
        }
        __syncthreads();
    }

    // split epilogue (128-wide tiles never cross split boundaries)
    float* Cb;
    int ld, coff;
    if (bn < split1)      { Cb = C0; ld = ld0; coff = bn; }
    else if (bn < split2) { Cb = C1; ld = ld1; coff = bn - split1; }
    else                  { Cb = C2; ld = ld2; coff = bn - split2; }

#pragma unroll
    for (int mf = 0; mf < 4; mf++) {
        int row = bm + warpM * 64 + mf * 16 + qr;
#pragma unroll
        for (int nf = 0; nf < 4; nf++) {
            int col = coff + warpN * 32 + nf * 8 + 2 * qk;
            float2* p0 = (float2*)(Cb + (size_t)row * ld + col);
            float2* p1 = (float2*)(Cb + (size_t)(row + 8) * ld + col);
            *p0 = make_float2(acc[mf][nf][0], acc[mf][nf][1]);
            *p1 = make_float2(acc[mf][nf][2], acc[mf][nf][3]);
        }
    }
}

// ----------------------------------------------------------------------------
// RoPE. If round_inplace: data gets tf32-rounded result. If rout != null:
// rout gets the tf32-rounded result (data keeps exact).
// ----------------------------------------------------------------------------
__global__ void rope_kernel(float* __restrict__ data,
                            float* __restrict__ rout,
                            const float* __restrict__ fc,
                            int rows, int heads, int round_inplace)
{
    int idx = blockIdx.x * blockDim.x + threadIdx.x;
    int total = rows * heads * 64;
    if (idx >= total) return;
    int i = idx & 63;
    int h = (idx >> 6) % heads;
    int row = idx / (heads * 64);
    int s = row & (SS - 1);
    float c = fc[(size_t)s * 128 + i * 2 + 0];
    float sn = fc[(size_t)s * 128 + i * 2 + 1];
    size_t off = (size_t)row * heads * HDD + h * HDD + i * 2;
    float* p = data + off;
    float xr = p[0], xi = p[1];
    float o0 = xr * c - xi * sn;
    float o1 = xr * sn + xi * c;
    float r0 = __uint_as_float(f2tf32(o0));
    float r1 = __uint_as_float(f2tf32(o1));
    if (round_inplace) {
        p[0] = r0;
        p[1] = r1;
    } else {
        p[0] = o0;
        p[1] = o1;
    }
    if (rout) {
        rout[off]     = r0;
        rout[off + 1] = r1;
    }
}

// ----------------------------------------------------------------------------
// Tensor-core flash attention (tf32 mma.sync), GQA-shared K/V.
// CTA = 64 A-rows = 4 heads x 16 queries; warp w owns head g*4+w.
// Epilogue writes ctx as HALF (feeds fp16 wo GEMM).
// ----------------------------------------------------------------------------
#define QS_OFF 0
#define KS_SZ  (64 * 132)
#define KS_OFF (64 * 132)
#define VS_SZ  (64 * 136)
#define VS_OFF (KS_OFF + 2 * KS_SZ)
#define P_OFF  (VS_OFF + 2 * VS_SZ)
#define ATT_SMEM_FLOATS (P_OFF + 64 * 72)   // 47360 floats = 189440 B

__global__ __launch_bounds__(128) void attn_mma_kernel(
    const float* __restrict__ Q, const float* __restrict__ K,
    const float* __restrict__ V, __half* __restrict__ O)
{
    extern __shared__ float sm[];

    const int tid  = threadIdx.x;
    const int lane = tid & 31;
    const int warp = tid >> 5;          // 0..3 == head_local
    const int qk = lane & 3;
    const int qr = lane >> 2;
    const int r0 = warp * 16 + qr;

    const int qt16 = blockIdx.x;
    const int g = blockIdx.y;
    const int b = blockIdx.z;

    const float* kbase = K + (size_t)b * SS * (NKVV * HDD) + g * HDD;
    const float* vbase = V + (size_t)b * SS * (NKVV * HDD) + g * HDD;

#pragma unroll
    for (int c = tid; c < 2048; c += 128) {
        int row = c >> 5, cc = c & 31;
        const float* src = Q + ((size_t)b * SS + qt16 * 16 + (row & 15)) * DIMM
                             + (g * 4 + (row >> 4)) * HDD + cc * 4;
        uint32_t dst = (uint32_t)__cvta_generic_to_shared(sm + QS_OFF + row * 132 + cc * 4);
        cp_async16(dst, src);
    }
    cp_commit();

    auto load_kv = [&](int t, int st) {
        const float* kb = kbase + (size_t)t * 64 * (NKVV * HDD);
        const float* vb = vbase + (size_t)t * 64 * (NKVV * HDD);
#pragma unroll
        for (int c = tid; c < 2048; c += 128) {
            int row = c >> 5, cc = c & 31;
            uint32_t dk = (uint32_t)__cvta_generic_to_shared(sm + KS_OFF + st * KS_SZ + row * 132 + cc * 4);
            cp_async16(dk, kb + (size_t)row * (NKVV * HDD) + cc * 4);
            uint32_t dv = (uint32_t)__cvta_generic_to_shared(sm + VS_OFF + st * VS_SZ + row * 136 + cc * 4);
            cp_async16(dv, vb + (size_t)row * (NKVV * HDD) + cc * 4);
        }
        cp_commit();
    };

    load_kv(0, 0);
    load_kv(1, 1);
    cp_wait<1>();
    __syncthreads();

    const float scale = 0.08838834764831845f;
    float m0 = -1e30f, m1 = -1e30f, l0 = 0.0f, l1 = 0.0f;
    float oacc[16][4];
#pragma unroll
    for (int nf = 0; nf < 16; nf++)
#pragma unroll
        for (int r = 0; r < 4; r++) oacc[nf][r] = 0.0f;

    const uint32_t* Qs = (const uint32_t*)(sm + QS_OFF);

    for (int t = 0; t < SS / 64; t++) {
        const int st = t & 1;
        const uint32_t* Ks = (const uint32_t*)(sm + KS_OFF + st * KS_SZ);
        const uint32_t* Vs = (const uint32_t*)(sm + VS_OFF + st * VS_SZ);
        uint32_t* P = (uint32_t*)(sm + P_OFF);

        float sacc[8][4];
#pragma unroll
        for (int nf = 0; nf < 8; nf++)
#pragma unroll
            for (int r = 0; r < 4; r++) sacc[nf][r] = 0.0f;

#pragma unroll
        for (int kf = 0; kf < 16; kf++) {
            const int k0 = kf * 8;
            uint32_t a0 = Qs[r0 * 132 + k0 + qk];
            uint32_t a1 = Qs[(r0 + 8) * 132 + k0 + qk];
            uint32_t a2 = Qs[r0 * 132 + k0 + qk + 4];
            uint32_t a3 = Qs[(r0 + 8) * 132 + k0 + qk + 4];
#pragma unroll
            for (int nf = 0; nf < 8; nf++) {
                uint32_t b0 = Ks[(nf * 8 + qr) * 132 + k0 + qk];
                uint32_t b1 = Ks[(nf * 8 + qr) * 132 + k0 + qk + 4];
                MMA_TF32(sacc[nf], a0, a1, a2, a3, b0, b1);
            }
        }

        float mx0 = -1e30f, mx1 = -1e30f;
#pragma unroll
        for (int nf = 0; nf < 8; nf++) {
            mx0 = fmaxf(mx0, fmaxf(sacc[nf][0], sacc[nf][1]));
            mx1 = fmaxf(mx1, fmaxf(sacc[nf][2], sacc[nf][3]));
        }
        mx0 *= scale;
        mx1 *= scale;
        mx0 = fmaxf(mx0, __shfl_xor_sync(0xffffffffu, mx0, 1));
        mx0 = fmaxf(mx0, __shfl_xor_sync(0xffffffffu, mx0, 2));
        mx1 = fmaxf(mx1, __shfl_xor_sync(0xffffffffu, mx1, 1));
        mx1 = fmaxf(mx1, __shfl_xor_sync(0xffffffffu, mx1, 2));

        float mn0 = fmaxf(m0, mx0), mn1 = fmaxf(m1, mx1);
        float cr0 = __expf(m0 - mn0), cr1 = __expf(m1 - mn1);
        float rs0 = 0.0f, rs1 = 0.0f;
#pragma unroll
        for (int nf = 0; nf < 8; nf++) {
            float p00 = __expf(sacc[nf][0] * scale - mn0);
            float p01 = __expf(sacc[nf][1] * scale - mn0);
            float p10 = __expf(sacc[nf][2] * scale - mn1);
            float p11 = __expf(sacc[nf][3] * scale - mn1);
            rs0 += p00 + p01;
            rs1 += p10 + p11;
            uint2* q0 = (uint2*)(P + r0 * 72 + nf * 8 + 2 * qk);
            uint2* q1 = (uint2*)(P + (r0 + 8) * 72 + nf * 8 + 2 * qk);
            *q0 = make_uint2(f2tf32(p00), f2tf32(p01));
            *q1 = make_uint2(f2tf32(p10), f2tf32(p11));
        }
        rs0 += __shfl_xor_sync(0xffffffffu, rs0, 1);
        rs0 += __shfl_xor_sync(0xffffffffu, rs0, 2);
        rs1 += __shfl_xor_sync(0xffffffffu, rs1, 1);
        rs1 += __shfl_xor_sync(0xffffffffu, rs1, 2);
        l0 = l0 * cr0 + rs0;
        l1 = l1 * cr1 + rs1;
        m0 = mn0;
        m1 = mn1;
#pragma unroll
        for (int nf = 0; nf < 16; nf++) {
            oacc[nf][0] *= cr0;
            oacc[nf][1] *= cr0;
            oacc[nf][2] *= cr1;
            oacc[nf][3] *= cr1;
        }
        __syncwarp();

#pragma unroll
        for (int kf = 0; kf < 8; kf++) {
            const int k0 = kf * 8;
            uint32_t a0 = P[r0 * 72 + k0 + qk];
            uint32_t a1 = P[(r0 + 8) * 72 + k0 + qk];
            uint32_t a2 = P[r0 * 72 + k0 + qk + 4];
            uint32_t a3 = P[(r0 + 8) * 72 + k0 + qk + 4];
#pragma unroll
            for (int nf = 0; nf < 16; nf++) {
                uint32_t b0 = Vs[(k0 + qk) * 136 + nf * 8 + qr];
                uint32_t b1 = Vs[(k0 + qk + 4) * 136 + nf * 8 + qr];
                MMA_TF32(oacc[nf], a0, a1, a2, a3, b0, b1);
            }
        }

        __syncthreads();
        if (t + 2 < SS / 64) {
            load_kv(t + 2, st);
            cp_wait<1>();
        } else if (t + 1 < SS / 64) {
            cp_wait<0>();
        }
        __syncthreads();
    }

    // epilogue: warp w -> head g*4+w; ctx written as HALF
    float inv0 = 1.0f / l0, inv1 = 1.0f / l1;
    __half* obase = O + ((size_t)b * SS + qt16 * 16) * DIMM + (g * 4 + warp) * HDD;
#pragma unroll
    for (int nf = 0; nf < 16; nf++) {
        int col = nf * 8 + 2 * qk;
        __half2* p0 = (__half2*)(obase + (size_t)qr * DIMM + col);
        __half2* p1 = (__half2*)(obase + (size_t)(qr + 8) * DIMM + col);
        *p0 = __floats2half2_rn(oacc[nf][0] * inv0, oacc[nf][1] * inv0);
        *p1 = __floats2half2_rn(oacc[nf][2] * inv1, oacc[nf][3] * inv1);
    }
}

// ----------------------------------------------------------------------------
// Launch
// ----------------------------------------------------------------------------
extern "C" void kernel_launch(void* const* d_in, const int* in_sizes, int n_in,
                              void* d_out, int out_size)
{
    const float* x  = (const float*)d_in[0];
    const float* fc = (const float*)d_in[1];
    const float* wq = (const float*)d_in[2];
    const float* wk = (const float*)d_in[3];
    const float* wv = (const float*)d_in[4];
    const float* wo = (const float*)d_in[5];

    float* out  = (float*)d_out;
    float* kout = out + (size_t)OUT_ELEMS;
    float* vout = kout + (size_t)KV_ELEMS;

    float *qptr, *kc, *vc;
    __half *ctxh, *xh, *wqkvh, *woh;
    cudaGetSymbolAddress((void**)&qptr, g_q);
    cudaGetSymbolAddress((void**)&ctxh, g_ctxh);
    cudaGetSymbolAddress((void**)&xh, g_xh);
    cudaGetSymbolAddress((void**)&wqkvh, g_wqkvh);
    cudaGetSymbolAddress((void**)&woh, g_woh);
    cudaGetSymbolAddress((void**)&kc, g_kc);
    cudaGetSymbolAddress((void**)&vc, g_vc);

    // x -> half; weights -> transposed [N][K] half (packed for QKV)
    {
        int n4x = OUT_ELEMS / 4;
        cvt_half_kernel<<<(n4x + 255) / 256, 256>>>(x, xh, n4x);
        dim3 tb(32, 8);
        dim3 tg_q(DIMM / 32, DIMM / 32);
        transpose_cvt_h_kernel<<<tg_q, tb>>>(wq, wqkvh, DIMM, DIMM, 0);
        dim3 tg_kv((NKVV * HDD) / 32, DIMM / 32);
        transpose_cvt_h_kernel<<<tg_kv, tb>>>(wk, wqkvh, DIMM, NKVV * HDD, DIMM);
        transpose_cvt_h_kernel<<<tg_kv, tb>>>(wv, wqkvh, DIMM, NKVV * HDD, DIMM + NKVV * HDD);
        transpose_cvt_h_kernel<<<tg_q, tb>>>(wo, woh, DIMM, DIMM, 0);
    }

    cudaFuncSetAttribute(gemm_f16_kernel,
                         cudaFuncAttributeMaxDynamicSharedMemorySize,
                         GEMM_SMEM_BYTES);

    // Merged Q/K/V projection: one fp16 GEMM, split epilogue
    {
        dim3 gg(NQKV / 128, MROWS / 128);   // 48 x 32
        gemm_f16_kernel<<<gg, 256, GEMM_SMEM_BYTES>>>(
            xh, wqkvh,
            qptr, DIMM, DIMM,
            kout, NKVV * HDD, DIMM + NKVV * HDD,
            vout, NKVV * HDD,
            MROWS, NQKV, DIMM);
    }

    // RoPE: Q rounded in place; K exact in place + rounded copy to kc
    {
        int totq = MROWS * NHH * 64;
        rope_kernel<<<(totq + 255) / 256, 256>>>(qptr, nullptr, fc, MROWS, NHH, 1);
        int totk = MROWS * NKVV * 64;
        rope_kernel<<<(totk + 255) / 256, 256>>>(kout, kc, fc, MROWS, NKVV, 0);
    }

    // Rounded V copy for attention
    {
        int n4 = KV_ELEMS / 4;
        cvt_tf32_kernel<<<(n4 + 255) / 256, 256>>>(vout, vc, n4);
    }

    // Attention (mma.sync flash, GQA-shared K/V) -> half ctx
    {
        size_t smem = ATT_SMEM_FLOATS * sizeof(float);
        cudaFuncSetAttribute(attn_mma_kernel,
                             cudaFuncAttributeMaxDynamicSharedMemorySize, (int)smem);
        dim3 grid(SS / 16, NKVV, BB);
        attn_mma_kernel<<<grid, 128, smem>>>(qptr, kc, vc, ctxh);
    }

    // Output projection (fp16 GEMM)
    {
        dim3 go(DIMM / 128, MROWS / 128);
        gemm_f16_kernel<<<go, 256, GEMM_SMEM_BYTES>>>(
            ctxh, woh,
            out, DIMM, DIMM,
            nullptr, 0, DIMM,
            nullptr, 0,
            MROWS, DIMM, DIMM);
    }
}

// round 11
// speedup vs baseline: 4.6683x; 1.3173x over previous
#include <cuda_runtime.h>
#include <cuda_fp16.h>
#include <math.h>
#include <stdint.h>

// Problem constants
#define BB   2
#define SS   2048
#define DIMM 4096
#define NHH  32
#define NKVV 8
#define HDD  128
#define MROWS (BB*SS)            // 4096
#define OUT_ELEMS   (MROWS*DIMM) // 16777216
#define KV_ELEMS    (MROWS*NKVV*HDD) // 4194304
#define NQKV (DIMM + 2 * NKVV * HDD)  // 6144 merged projection width

// Scratch (device globals -- no allocation allowed)
__device__ float  g_q[(size_t)MROWS * DIMM];      // Q pre-rope fp32 (GEMM out)
__device__ __half g_qh[(size_t)MROWS * DIMM];     // roped Q, half (attn input)
__device__ __half g_kh[(size_t)KV_ELEMS];         // roped K, half (attn input)
__device__ __half g_vt[(size_t)KV_ELEMS];         // V^T [b][g][d][S], half
__device__ __half g_ctxh[(size_t)MROWS * DIMM];   // ctx (half, from attn epilogue)
__device__ __half g_xh[(size_t)MROWS * DIMM];     // x, half
__device__ __half g_wqkvh[(size_t)NQKV * DIMM];   // [wq|wk|wv]^T packed, [N][K] half
__device__ __half g_woh[(size_t)DIMM * DIMM];     // wo^T, [N][K] half

__device__ __forceinline__ void cp_async16(uint32_t dst, const void* src) {
    asm volatile("cp.async.ca.shared.global [%0], [%1], 16;\n" :: "r"(dst), "l"(src));
}
__device__ __forceinline__ void cp_commit() {
    asm volatile("cp.async.commit_group;\n");
}
template <int W>
__device__ __forceinline__ void cp_wait() {
    asm volatile("cp.async.wait_group %0;\n" :: "n"(W));
}

#define MMA_F16(acc, a0, a1, a2, a3, b0, b1)                                   \
    asm volatile(                                                              \
        "mma.sync.aligned.m16n8k16.row.col.f32.f16.f16.f32 "                   \
        "{%0,%1,%2,%3}, {%4,%5,%6,%7}, {%8,%9}, {%0,%1,%2,%3};"                \
        : "+f"((acc)[0]), "+f"((acc)[1]), "+f"((acc)[2]), "+f"((acc)[3])       \
        : "r"(a0), "r"(a1), "r"(a2), "r"(a3), "r"(b0), "r"(b1))

// ----------------------------------------------------------------------------
// Elementwise fp32 -> half
// ----------------------------------------------------------------------------
__global__ void cvt_half_kernel(const float* __restrict__ in,
                                __half* __restrict__ out, int n4)
{
    int i = blockIdx.x * blockDim.x + threadIdx.x;
    if (i >= n4) return;
    float4 v = ((const float4*)in)[i];
    ((__half2*)out)[i * 2]     = __floats2half2_rn(v.x, v.y);
    ((__half2*)out)[i * 2 + 1] = __floats2half2_rn(v.z, v.w);
}

// ----------------------------------------------------------------------------
// Transpose + half convert: in [K][Nin] fp32 -> out[(coff+n)][K] half
// ----------------------------------------------------------------------------
__global__ void transpose_cvt_h_kernel(const float* __restrict__ in,
                                       __half* __restrict__ out,
                                       int K, int Nin, int coff)
{
    __shared__ float tile[32][33];
    int x = blockIdx.x * 32 + threadIdx.x;
    int y0 = blockIdx.y * 32;
#pragma unroll
    for (int i = threadIdx.y; i < 32; i += 8)
        tile[i][threadIdx.x] = in[(size_t)(y0 + i) * Nin + x];
    __syncthreads();
    int xo = y0 + threadIdx.x;
    int yo0 = coff + blockIdx.x * 32;
#pragma unroll
    for (int i = threadIdx.y; i < 32; i += 8)
        out[(size_t)(yo0 + i) * K + xo] = __float2half_rn(tile[threadIdx.x][i]);
}

// ----------------------------------------------------------------------------
// V transpose for attention: vout (b,s,g,d) fp32 -> g_vt (b,g,d,s) half
// block (32,8), grid (SS/32, HDD/32, BB*NKVV)
// ----------------------------------------------------------------------------
__global__ void transpose_v_kernel(const float* __restrict__ in,
                                   __half* __restrict__ out)
{
    __shared__ float tile[32][33];
    int bg = blockIdx.z;
    int b = bg >> 3, g = bg & 7;
    int s0 = blockIdx.x * 32, d0 = blockIdx.y * 32;
#pragma unroll
    for (int i = threadIdx.y; i < 32; i += 8)
        tile[i][threadIdx.x] =
            in[((size_t)(b * SS + s0 + i)) * (NKVV * HDD) + g * HDD + d0 + threadIdx.x];
    __syncthreads();
#pragma unroll
    for (int i = threadIdx.y; i < 32; i += 8)
        out[((size_t)((b * NKVV + g) * HDD) + d0 + i) * SS + s0 + threadIdx.x] =
            __float2half_rn(tile[threadIdx.x][i]);
}

// ----------------------------------------------------------------------------
// FP16 tensor-core GEMM with split epilogue (proven R9 kernel).
// ----------------------------------------------------------------------------
#define BKH 64
#define STRH 72
#define STAGE_H (128 * STRH)
#define GEMM_SMEM_BYTES (4 * STAGE_H * 2)   // 73728

__global__ __launch_bounds__(256) void gemm_f16_kernel(
    const __half* __restrict__ A, const __half* __restrict__ BT,
    float* __restrict__ C0, int ld0, int split1,
    float* __restrict__ C1, int ld1, int split2,
    float* __restrict__ C2, int ld2,
    int M, int N, int K)
{
    extern __shared__ __half smh[];
    __half* AsB = smh;
    __half* BsB = smh + 2 * STAGE_H;

    const int tid   = threadIdx.x;
    const int lane  = tid & 31;
    const int warp  = tid >> 5;
    const int warpM = warp >> 2;
    const int warpN = warp & 3;
    const int bm = blockIdx.y * 128;
    const int bn = blockIdx.x * 128;

    const int qk = lane & 3;
    const int qr = lane >> 2;

    const int ntiles = K / BKH;

    float acc[4][4][4];
#pragma unroll
    for (int i = 0; i < 4; i++)
#pragma unroll
        for (int j = 0; j < 4; j++)
#pragma unroll
            for (int r = 0; r < 4; r++) acc[i][j][r] = 0.0f;

    auto load_tile = [&](int t, int st) {
        const __half* Asrc = A + (size_t)bm * K + t * BKH;
        __half* Ad = AsB + st * STAGE_H;
#pragma unroll
        for (int l = 0; l < 4; l++) {
            int flat = l * 256 + tid;
            int row = flat >> 3;
            int cg  = flat & 7;
            uint32_t dst = (uint32_t)__cvta_generic_to_shared(Ad + row * STRH + cg * 8);
            cp_async16(dst, Asrc + (size_t)row * K + cg * 8);
        }
        const __half* Bsrc = BT + (size_t)bn * K + t * BKH;
        __half* Bd = BsB + st * STAGE_H;
#pragma unroll
        for (int l = 0; l < 4; l++) {
            int flat = l * 256 + tid;
            int row = flat >> 3;
            int cg  = flat & 7;
            uint32_t dst = (uint32_t)__cvta_generic_to_shared(Bd + row * STRH + cg * 8);
            cp_async16(dst, Bsrc + (size_t)row * K + cg * 8);
        }
        cp_commit();
    };

    load_tile(0, 0);

    for (int t = 0; t < ntiles; t++) {
        const int st = t & 1;
        if (t + 1 < ntiles) {
            load_tile(t + 1, st ^ 1);
            cp_wait<1>();
        } else {
            cp_wait<0>();
        }
        __syncthreads();

        const uint32_t* As = (const uint32_t*)(AsB + st * STAGE_H);
        const uint32_t* Bs = (const uint32_t*)(BsB + st * STAGE_H);

#pragma unroll
        for (int kk2 = 0; kk2 < 32; kk2 += 8) {
            uint32_t af[4][4], bf[4][2];
#pragma unroll
            for (int mf = 0; mf < 4; mf++) {
                int row = warpM * 64 + mf * 16 + qr;
                af[mf][0] = As[row * 36 + kk2 + qk];
                af[mf][1] = As[(row + 8) * 36 + kk2 + qk];
                af[mf][2] = As[row * 36 + kk2 + qk + 4];
                af[mf][3] = As[(row + 8) * 36 + kk2 + qk + 4];
            }
#pragma unroll
            for (int nf = 0; nf < 4; nf++) {
                int col = warpN * 32 + nf * 8 + qr;
                bf[nf][0] = Bs[col * 36 + kk2 + qk];
                bf[nf][1] = Bs[col * 36 + kk2 + qk + 4];
            }
#pragma unroll
            for (int mf = 0; mf < 4; mf++)
#pragma unroll
                for (int nf = 0; nf < 4; nf++)
                    MMA_F16(acc[mf][nf], af[mf][0], af[mf][1], af[mf][2], af[mf][3],
                            bf[nf][0], bf[nf][1]);
        }
        __syncthreads();
    }

    float* Cb;
    int ld, coff;
    if (bn < split1)      { Cb = C0; ld = ld0; coff = bn; }
    else if (bn < split2) { Cb = C1; ld = ld1; coff = bn - split1; }
    else                  { Cb = C2; ld = ld2; coff = bn - split2; }

#pragma unroll
    for (int mf = 0; mf < 4; mf++) {
        int row = bm + warpM * 64 + mf * 16 + qr;
#pragma unroll
        for (int nf = 0; nf < 4; nf++) {
            int col = coff + warpN * 32 + nf * 8 + 2 * qk;
            float2* p0 = (float2*)(Cb + (size_t)row * ld + col);
            float2* p1 = (float2*)(Cb + (size_t)(row + 8) * ld + col);
            *p0 = make_float2(acc[mf][nf][0], acc[mf][nf][1]);
            *p1 = make_float2(acc[mf][nf][2], acc[mf][nf][3]);
        }
    }
}

// ----------------------------------------------------------------------------
// RoPE Q: read fp32 (GEMM out), write HALF roped Q.
// ----------------------------------------------------------------------------
__global__ void rope_q_kernel(const float* __restrict__ in,
                              __half* __restrict__ out,
                              const float* __restrict__ fc)
{
    int idx = blockIdx.x * blockDim.x + threadIdx.x;
    int total = MROWS * NHH * 64;
    if (idx >= total) return;
    int i = idx & 63;
    int h = (idx >> 6) % NHH;
    int row = idx / (NHH * 64);
    int s = row & (SS - 1);
    float c = fc[(size_t)s * 128 + i * 2 + 0];
    float sn = fc[(size_t)s * 128 + i * 2 + 1];
    size_t off = (size_t)row * NHH * HDD + h * HDD + i * 2;
    float xr = in[off], xi = in[off + 1];
    *(__half2*)(out + off) = __floats2half2_rn(xr * c - xi * sn, xr * sn + xi * c);
}

// ----------------------------------------------------------------------------
// RoPE K: in-place exact fp32 (new_k output) + half copy for attention.
// ----------------------------------------------------------------------------
__global__ void rope_k_kernel(float* __restrict__ data,
                              __half* __restrict__ hout,
                              const float* __restrict__ fc)
{
    int idx = blockIdx.x * blockDim.x + threadIdx.x;
    int total = MROWS * NKVV * 64;
    if (idx >= total) return;
    int i = idx & 63;
    int h = (idx >> 6) % NKVV;
    int row = idx / (NKVV * 64);
    int s = row & (SS - 1);
    float c = fc[(size_t)s * 128 + i * 2 + 0];
    float sn = fc[(size_t)s * 128 + i * 2 + 1];
    size_t off = (size_t)row * NKVV * HDD + h * HDD + i * 2;
    float xr = data[off], xi = data[off + 1];
    float o0 = xr * c - xi * sn;
    float o1 = xr * sn + xi * c;
    data[off]     = o0;
    data[off + 1] = o1;
    *(__half2*)(hout + off) = __floats2half2_rn(o0, o1);
}

// ----------------------------------------------------------------------------
// FP16 tensor-core flash attention, GQA-shared K/V.
// CTA = 64 A-rows = 4 heads x 16 queries; warp w owns head g*4+w.
// smem (halves): Qs[64][136] | Ks[2][64][136] | Vt[2][128][72] | P[64][72]
// Q/K rows: 128 halves (d), stride 136 halves (68 words).
// Vt rows: d, 64 halves (keys), stride 72 halves (36 words).
// ----------------------------------------------------------------------------
#define AQS_OFF 0
#define AKS_SZ  (64 * 136)
#define AKS_OFF (64 * 136)
#define AVT_SZ  (128 * 72)
#define AVT_OFF (AKS_OFF + 2 * AKS_SZ)
#define AP_OFF  (AVT_OFF + 2 * AVT_SZ)
#define ATT_SMEM_HALVES (AP_OFF + 64 * 72)   // 49152 halves = 98304 B

__global__ __launch_bounds__(128) void attn_f16_kernel(
    const __half* __restrict__ Q, const __half* __restrict__ K,
    const __half* __restrict__ Vt, __half* __restrict__ O)
{
    extern __shared__ __half smh[];

    const int tid  = threadIdx.x;
    const int lane = tid & 31;
    const int warp = tid >> 5;          // 0..3 == head_local
    const int qk = lane & 3;
    const int qr = lane >> 2;
    const int r0 = warp * 16 + qr;

    const int qt16 = blockIdx.x;
    const int g = blockIdx.y;
    const int b = blockIdx.z;

    const __half* kbase = K + (size_t)b * SS * (NKVV * HDD) + g * HDD;
    const __half* vtbase = Vt + (size_t)(b * NKVV + g) * HDD * SS;

    // Q tile: 64 rows x 128 halves (16 chunks of 8 halves per row)
#pragma unroll
    for (int c = tid; c < 1024; c += 128) {
        int row = c >> 4, cc = c & 15;
        const __half* src = Q + ((size_t)b * SS + qt16 * 16 + (row & 15)) * DIMM
                              + (g * 4 + (row >> 4)) * HDD + cc * 8;
        uint32_t dst = (uint32_t)__cvta_generic_to_shared(smh + AQS_OFF + row * 136 + cc * 8);
        cp_async16(dst, src);
    }
    cp_commit();

    auto load_kv = [&](int t, int st) {
        const __half* kb = kbase + (size_t)t * 64 * (NKVV * HDD);
#pragma unroll
        for (int c = tid; c < 1024; c += 128) {
            int row = c >> 4, cc = c & 15;
            uint32_t dk = (uint32_t)__cvta_generic_to_shared(
                smh + AKS_OFF + st * AKS_SZ + row * 136 + cc * 8);
            cp_async16(dk, kb + (size_t)row * (NKVV * HDD) + cc * 8);
        }
        const __half* vb = vtbase + t * 64;
#pragma unroll
        for (int c = tid; c < 1024; c += 128) {
            int row = c >> 3, cc = c & 7;   // 128 d-rows x 8 chunks
            uint32_t dv = (uint32_t)__cvta_generic_to_shared(
                smh + AVT_OFF + st * AVT_SZ + row * 72 + cc * 8);
            cp_async16(dv, vb + (size_t)row * SS + cc * 8);
        }
        cp_commit();
    };

    load_kv(0, 0);
    load_kv(1, 1);
    cp_wait<1>();
    __syncthreads();

    const float scale = 0.08838834764831845f;
    float m0 = -1e30f, m1 = -1e30f, l0 = 0.0f, l1 = 0.0f;
    float oacc[16][4];
#pragma unroll
    for (int nf = 0; nf < 16; nf++)
#pragma unroll
        for (int r = 0; r < 4; r++) oacc[nf][r] = 0.0f;

    const uint32_t* Qw = (const uint32_t*)(smh + AQS_OFF);

    for (int t = 0; t < SS / 64; t++) {
        const int st = t & 1;
        const uint32_t* Kw = (const uint32_t*)(smh + AKS_OFF + st * AKS_SZ);
        const uint32_t* Vw = (const uint32_t*)(smh + AVT_OFF + st * AVT_SZ);
        __half* Ph = smh + AP_OFF;

        // ---- S = Q K^T (this warp: 16 rows x 64 keys), fp16 k16 ----
        float sacc[8][4];
#pragma unroll
        for (int nf = 0; nf < 8; nf++)
#pragma unroll
            for (int r = 0; r < 4; r++) sacc[nf][r] = 0.0f;

#pragma unroll
        for (int kf = 0; kf < 8; kf++) {
            const int kk2 = kf * 8;       // word offset (8 words = 16 halves)
            uint32_t a0 = Qw[r0 * 68 + kk2 + qk];
            uint32_t a1 = Qw[(r0 + 8) * 68 + kk2 + qk];
            uint32_t a2 = Qw[r0 * 68 + kk2 + qk + 4];
            uint32_t a3 = Qw[(r0 + 8) * 68 + kk2 + qk + 4];
#pragma unroll
            for (int nf = 0; nf < 8; nf++) {
                int col = nf * 8 + qr;
                uint32_t b0 = Kw[col * 68 + kk2 + qk];
                uint32_t b1 = Kw[col * 68 + kk2 + qk + 4];
                MMA_F16(sacc[nf], a0, a1, a2, a3, b0, b1);
            }
        }

        // ---- online softmax ----
        float mx0 = -1e30f, mx1 = -1e30f;
#pragma unroll
        for (int nf = 0; nf < 8; nf++) {
            mx0 = fmaxf(mx0, fmaxf(sacc[nf][0], sacc[nf][1]));
            mx1 = fmaxf(mx1, fmaxf(sacc[nf][2], sacc[nf][3]));
        }
        mx0 *= scale;
        mx1 *= scale;
        mx0 = fmaxf(mx0, __shfl_xor_sync(0xffffffffu, mx0, 1));
        mx0 = fmaxf(mx0, __shfl_xor_sync(0xffffffffu, mx0, 2));
        mx1 = fmaxf(mx1, __shfl_xor_sync(0xffffffffu, mx1, 1));
        mx1 = fmaxf(mx1, __shfl_xor_sync(0xffffffffu, mx1, 2));

        float mn0 = fmaxf(m0, mx0), mn1 = fmaxf(m1, mx1);
        float cr0 = __expf(m0 - mn0), cr1 = __expf(m1 - mn1);
        float rs0 = 0.0f, rs1 = 0.0f;
#pragma unroll
        for (int nf = 0; nf < 8; nf++) {
            float p00 = __expf(sacc[nf][0] * scale - mn0);
            float p01 = __expf(sacc[nf][1] * scale - mn0);
            float p10 = __expf(sacc[nf][2] * scale - mn1);
            float p11 = __expf(sacc[nf][3] * scale - mn1);
            rs0 += p00 + p01;
            rs1 += p10 + p11;
            *(__half2*)(Ph + r0 * 72 + nf * 8 + 2 * qk)       = __floats2half2_rn(p00, p01);
            *(__half2*)(Ph + (r0 + 8) * 72 + nf * 8 + 2 * qk) = __floats2half2_rn(p10, p11);
        }
        rs0 += __shfl_xor_sync(0xffffffffu, rs0, 1);
        rs0 += __shfl_xor_sync(0xffffffffu, rs0, 2);
        rs1 += __shfl_xor_sync(0xffffffffu, rs1, 1);
        rs1 += __shfl_xor_sync(0xffffffffu, rs1, 2);
        l0 = l0 * cr0 + rs0;
        l1 = l1 * cr1 + rs1;
        m0 = mn0;
        m1 = mn1;
#pragma unroll
        for (int nf = 0; nf < 16; nf++) {
            oacc[nf][0] *= cr0;
            oacc[nf][1] *= cr0;
            oacc[nf][2] *= cr1;
            oacc[nf][3] *= cr1;
        }
        __syncwarp();   // P rows are private to this warp; order STS->LDS

        // ---- O += P V  (P: 16x64 half, Vt: 128 d-cols x 64 keys) ----
        const uint32_t* Pw = (const uint32_t*)(smh + AP_OFF);
#pragma unroll
        for (int kf = 0; kf < 4; kf++) {
            const int kk2 = kf * 8;       // 8 words = 16 keys
            uint32_t a0 = Pw[r0 * 36 + kk2 + qk];
            uint32_t a1 = Pw[(r0 + 8) * 36 + kk2 + qk];
            uint32_t a2 = Pw[r0 * 36 + kk2 + qk + 4];
            uint32_t a3 = Pw[(r0 + 8) * 36 + kk2 + qk + 4];
#pragma unroll
            for (int nf = 0; nf < 16; nf++) {
                int col = nf * 8 + qr;    // d index
                uint32_t b0 = Vw[col * 36 + kk2 + qk];
                uint32_t b1 = Vw[col * 36 + kk2 + qk + 4];
                MMA_F16(oacc[nf], a0, a1, a2, a3, b0, b1);
            }
        }

        __syncthreads();
        if (t + 2 < SS / 64) {
            load_kv(t + 2, st);
            cp_wait<1>();
        } else if (t + 1 < SS / 64) {
            cp_wait<0>();
        }
        __syncthreads();
    }

    // epilogue: warp w -> head g*4+w; ctx written as HALF
    float inv0 = 1.0f / l0, inv1 = 1.0f / l1;
    __half* obase = O + ((size_t)b * SS + qt16 * 16) * DIMM + (g * 4 + warp) * HDD;
#pragma unroll
    for (int nf = 0; nf < 16; nf++) {
        int col = nf * 8 + 2 * qk;
        __half2* p0 = (__half2*)(obase + (size_t)qr * DIMM + col);
        __half2* p1 = (__half2*)(obase + (size_t)(qr + 8) * DIMM + col);
        *p0 = __floats2half2_rn(oacc[nf][0] * inv0, oacc[nf][1] * inv0);
        *p1 = __floats2half2_rn(oacc[nf][2] * inv1, oacc[nf][3] * inv1);
    }
}

// ----------------------------------------------------------------------------
// Launch
// ----------------------------------------------------------------------------
extern "C" void kernel_launch(void* const* d_in, const int* in_sizes, int n_in,
                              void* d_out, int out_size)
{
    const float* x  = (const float*)d_in[0];
    const float* fc = (const float*)d_in[1];
    const float* wq = (const float*)d_in[2];
    const float* wk = (const float*)d_in[3];
    const float* wv = (const float*)d_in[4];
    const float* wo = (const float*)d_in[5];

    float* out  = (float*)d_out;
    float* kout = out + (size_t)OUT_ELEMS;
    float* vout = kout + (size_t)KV_ELEMS;

    float *qptr;
    __half *qh, *kh, *vt, *ctxh, *xh, *wqkvh, *woh;
    cudaGetSymbolAddress((void**)&qptr, g_q);
    cudaGetSymbolAddress((void**)&qh, g_qh);
    cudaGetSymbolAddress((void**)&kh, g_kh);
    cudaGetSymbolAddress((void**)&vt, g_vt);
    cudaGetSymbolAddress((void**)&ctxh, g_ctxh);
    cudaGetSymbolAddress((void**)&xh, g_xh);
    cudaGetSymbolAddress((void**)&wqkvh, g_wqkvh);
    cudaGetSymbolAddress((void**)&woh, g_woh);

    // x -> half; weights -> transposed [N][K] half (packed for QKV)
    {
        int n4x = OUT_ELEMS / 4;
        cvt_half_kernel<<<(n4x + 255) / 256, 256>>>(x, xh, n4x);
        dim3 tb(32, 8);
        dim3 tg_q(DIMM / 32, DIMM / 32);
        transpose_cvt_h_kernel<<<tg_q, tb>>>(wq, wqkvh, DIMM, DIMM, 0);
        dim3 tg_kv((NKVV * HDD) / 32, DIMM / 32);
        transpose_cvt_h_kernel<<<tg_kv, tb>>>(wk, wqkvh, DIMM, NKVV * HDD, DIMM);
        transpose_cvt_h_kernel<<<tg_kv, tb>>>(wv, wqkvh, DIMM, NKVV * HDD, DIMM + NKVV * HDD);
        transpose_cvt_h_kernel<<<tg_q, tb>>>(wo, woh, DIMM, DIMM, 0);
    }

    cudaFuncSetAttribute(gemm_f16_kernel,
                         cudaFuncAttributeMaxDynamicSharedMemorySize,
                         GEMM_SMEM_BYTES);

    // Merged Q/K/V projection: one fp16 GEMM, split epilogue
    {
        dim3 gg(NQKV / 128, MROWS / 128);
        gemm_f16_kernel<<<gg, 256, GEMM_SMEM_BYTES>>>(
            xh, wqkvh,
            qptr, DIMM, DIMM,
            kout, NKVV * HDD, DIMM + NKVV * HDD,
            vout, NKVV * HDD,
            MROWS, NQKV, DIMM);
    }

    // RoPE: Q -> half; K exact in place + half copy; V -> transposed half
    {
        int totq = MROWS * NHH * 64;
        rope_q_kernel<<<(totq + 255) / 256, 256>>>(qptr, qh, fc);
        int totk = MROWS * NKVV * 64;
        rope_k_kernel<<<(totk + 255) / 256, 256>>>(kout, kh, fc);
        dim3 tb(32, 8);
        dim3 tv(SS / 32, HDD / 32, BB * NKVV);
        transpose_v_kernel<<<tv, tb>>>(vout, vt);
    }

    // Attention (fp16 mma flash, GQA-shared K/V) -> half ctx
    {
        size_t smem = ATT_SMEM_HALVES * sizeof(__half);  // 98304 B
        cudaFuncSetAttribute(attn_f16_kernel,
                             cudaFuncAttributeMaxDynamicSharedMemorySize, (int)smem);
        dim3 grid(SS / 16, NKVV, BB);
        attn_f16_kernel<<<grid, 128, smem>>>(qh, kh, vt, ctxh);
    }

    // Output projection (fp16 GEMM)
    {
        dim3 go(DIMM / 128, MROWS / 128);
        gemm_f16_kernel<<<go, 256, GEMM_SMEM_BYTES>>>(
            ctxh, woh,
            out, DIMM, DIMM,
            nullptr, 0, DIMM,
            nullptr, 0,
            MROWS, DIMM, DIMM);
    }
}

// round 12
// speedup vs baseline: 4.6910x; 1.0049x over previous
#include <cuda_runtime.h>
#include <cuda_fp16.h>
#include <math.h>
#include <stdint.h>

// Problem constants
#define BB   2
#define SS   2048
#define DIMM 4096
#define NHH  32
#define NKVV 8
#define HDD  128
#define MROWS (BB*SS)            // 4096
#define OUT_ELEMS   (MROWS*DIMM) // 16777216
#define KV_ELEMS    (MROWS*NKVV*HDD) // 4194304
#define NQKV (DIMM + 2 * NKVV * HDD)  // 6144 merged projection width

// Scratch (device globals -- no allocation allowed)
__device__ __half g_qh[(size_t)MROWS * DIMM];     // roped Q, half (attn input)
__device__ __half g_kh[(size_t)KV_ELEMS];         // roped K, half (attn input)
__device__ __half g_vt[(size_t)KV_ELEMS];         // V^T [b][g][d][S], half
__device__ __half g_ctxh[(size_t)MROWS * DIMM];   // ctx (half, from attn epilogue)
__device__ __half g_xh[(size_t)MROWS * DIMM];     // x, half
__device__ __half g_wqkvh[(size_t)NQKV * DIMM];   // [wq|wk|wv]^T packed, [N][K] half
__device__ __half g_woh[(size_t)DIMM * DIMM];     // wo^T, [N][K] half

__device__ __forceinline__ void cp_async16(uint32_t dst, const void* src) {
    asm volatile("cp.async.ca.shared.global [%0], [%1], 16;\n" :: "r"(dst), "l"(src));
}
__device__ __forceinline__ void cp_commit() {
    asm volatile("cp.async.commit_group;\n");
}
template <int W>
__device__ __forceinline__ void cp_wait() {
    asm volatile("cp.async.wait_group %0;\n" :: "n"(W));
}

#define MMA_F16(acc, a0, a1, a2, a3, b0, b1)                                   \
    asm volatile(                                                              \
        "mma.sync.aligned.m16n8k16.row.col.f32.f16.f16.f32 "                   \
        "{%0,%1,%2,%3}, {%4,%5,%6,%7}, {%8,%9}, {%0,%1,%2,%3};"                \
        : "+f"((acc)[0]), "+f"((acc)[1]), "+f"((acc)[2]), "+f"((acc)[3])       \
        : "r"(a0), "r"(a1), "r"(a2), "r"(a3), "r"(b0), "r"(b1))

// ----------------------------------------------------------------------------
// Elementwise fp32 -> half
// ----------------------------------------------------------------------------
__global__ void cvt_half_kernel(const float* __restrict__ in,
                                __half* __restrict__ out, int n4)
{
    int i = blockIdx.x * blockDim.x + threadIdx.x;
    if (i >= n4) return;
    float4 v = ((const float4*)in)[i];
    ((__half2*)out)[i * 2]     = __floats2half2_rn(v.x, v.y);
    ((__half2*)out)[i * 2 + 1] = __floats2half2_rn(v.z, v.w);
}

// ----------------------------------------------------------------------------
// Transpose + half convert: in [K][Nin] fp32 -> out[(coff+n)][K] half
// ----------------------------------------------------------------------------
__global__ void transpose_cvt_h_kernel(const float* __restrict__ in,
                                       __half* __restrict__ out,
                                       int K, int Nin, int coff)
{
    __shared__ float tile[32][33];
    int x = blockIdx.x * 32 + threadIdx.x;
    int y0 = blockIdx.y * 32;
#pragma unroll
    for (int i = threadIdx.y; i < 32; i += 8)
        tile[i][threadIdx.x] = in[(size_t)(y0 + i) * Nin + x];
    __syncthreads();
    int xo = y0 + threadIdx.x;
    int yo0 = coff + blockIdx.x * 32;
#pragma unroll
    for (int i = threadIdx.y; i < 32; i += 8)
        out[(size_t)(yo0 + i) * K + xo] = __float2half_rn(tile[threadIdx.x][i]);
}

// ----------------------------------------------------------------------------
// V transpose for attention: vout (b,s,g,d) fp32 -> g_vt (b,g,d,s) half
// block (32,8), grid (SS/32, HDD/32, BB*NKVV)
// ----------------------------------------------------------------------------
__global__ void transpose_v_kernel(const float* __restrict__ in,
                                   __half* __restrict__ out)
{
    __shared__ float tile[32][33];
    int bg = blockIdx.z;
    int b = bg >> 3, g = bg & 7;
    int s0 = blockIdx.x * 32, d0 = blockIdx.y * 32;
#pragma unroll
    for (int i = threadIdx.y; i < 32; i += 8)
        tile[i][threadIdx.x] =
            in[((size_t)(b * SS + s0 + i)) * (NKVV * HDD) + g * HDD + d0 + threadIdx.x];
    __syncthreads();
#pragma unroll
    for (int i = threadIdx.y; i < 32; i += 8)
        out[((size_t)((b * NKVV + g) * HDD) + d0 + i) * SS + s0 + threadIdx.x] =
            __float2half_rn(tile[threadIdx.x][i]);
}

// ----------------------------------------------------------------------------
// FP16 tensor-core GEMM.
// mode 0: C = A*BT^T fp32 to outF (ld DIMM)     [wo projection]
// mode 1: fused QKV epilogue with RoPE:
//         cols [0,4096):    rope -> half qh
//         cols [4096,5120): rope -> fp32 kout (new_k) + half kh
//         cols [5120,6144): fp32 vout (new_v)
// ----------------------------------------------------------------------------
#define BKH 64
#define STRH 72
#define STAGE_H (128 * STRH)
#define GEMM_SMEM_BYTES (4 * STAGE_H * 2)   // 73728

__global__ __launch_bounds__(256) void gemm_f16_kernel(
    const __half* __restrict__ A, const __half* __restrict__ BT,
    const float* __restrict__ fc,
    __half* __restrict__ qh,
    float* __restrict__ kout, __half* __restrict__ kh,
    float* __restrict__ vout,
    float* __restrict__ outF,
    int M, int N, int K, int mode)
{
    extern __shared__ __half smh[];
    __half* AsB = smh;
    __half* BsB = smh + 2 * STAGE_H;

    const int tid   = threadIdx.x;
    const int lane  = tid & 31;
    const int warp  = tid >> 5;
    const int warpM = warp >> 2;
    const int warpN = warp & 3;
    const int bm = blockIdx.y * 128;
    const int bn = blockIdx.x * 128;

    const int qk = lane & 3;
    const int qr = lane >> 2;

    const int ntiles = K / BKH;

    float acc[4][4][4];
#pragma unroll
    for (int i = 0; i < 4; i++)
#pragma unroll
        for (int j = 0; j < 4; j++)
#pragma unroll
            for (int r = 0; r < 4; r++) acc[i][j][r] = 0.0f;

    auto load_tile = [&](int t, int st) {
        const __half* Asrc = A + (size_t)bm * K + t * BKH;
        __half* Ad = AsB + st * STAGE_H;
#pragma unroll
        for (int l = 0; l < 4; l++) {
            int flat = l * 256 + tid;
            int row = flat >> 3;
            int cg  = flat & 7;
            uint32_t dst = (uint32_t)__cvta_generic_to_shared(Ad + row * STRH + cg * 8);
            cp_async16(dst, Asrc + (size_t)row * K + cg * 8);
        }
        const __half* Bsrc = BT + (size_t)bn * K + t * BKH;
        __half* Bd = BsB + st * STAGE_H;
#pragma unroll
        for (int l = 0; l < 4; l++) {
            int flat = l * 256 + tid;
            int row = flat >> 3;
            int cg  = flat & 7;
            uint32_t dst = (uint32_t)__cvta_generic_to_shared(Bd + row * STRH + cg * 8);
            cp_async16(dst, Bsrc + (size_t)row * K + cg * 8);
        }
        cp_commit();
    };

    load_tile(0, 0);

    for (int t = 0; t < ntiles; t++) {
        const int st = t & 1;
        if (t + 1 < ntiles) {
            load_tile(t + 1, st ^ 1);
            cp_wait<1>();
        } else {
            cp_wait<0>();
        }
        __syncthreads();

        const uint32_t* As = (const uint32_t*)(AsB + st * STAGE_H);
        const uint32_t* Bs = (const uint32_t*)(BsB + st * STAGE_H);

#pragma unroll
        for (int kk2 = 0; kk2 < 32; kk2 += 8) {
            uint32_t af[4][4], bf[4][2];
#pragma unroll
            for (int mf = 0; mf < 4; mf++) {
                int row = warpM * 64 + mf * 16 + qr;
                af[mf][0] = As[row * 36 + kk2 + qk];
                af[mf][1] = As[(row + 8) * 36 + kk2 + qk];
                af[mf][2] = As[row * 36 + kk2 + qk + 4];
                af[mf][3] = As[(row + 8) * 36 + kk2 + qk + 4];
            }
#pragma unroll
            for (int nf = 0; nf < 4; nf++) {
                int col = warpN * 32 + nf * 8 + qr;
                bf[nf][0] = Bs[col * 36 + kk2 + qk];
                bf[nf][1] = Bs[col * 36 + kk2 + qk + 4];
            }
#pragma unroll
            for (int mf = 0; mf < 4; mf++)
#pragma unroll
                for (int nf = 0; nf < 4; nf++)
                    MMA_F16(acc[mf][nf], af[mf][0], af[mf][1], af[mf][2], af[mf][3],
                            bf[nf][0], bf[nf][1]);
        }
        __syncthreads();
    }

    if (mode == 0) {
        // plain fp32 epilogue (wo projection)
#pragma unroll
        for (int mf = 0; mf < 4; mf++) {
            int row = bm + warpM * 64 + mf * 16 + qr;
#pragma unroll
            for (int nf = 0; nf < 4; nf++) {
                int col = bn + warpN * 32 + nf * 8 + 2 * qk;
                float2* p0 = (float2*)(outF + (size_t)row * DIMM + col);
                float2* p1 = (float2*)(outF + (size_t)(row + 8) * DIMM + col);
                *p0 = make_float2(acc[mf][nf][0], acc[mf][nf][1]);
                *p1 = make_float2(acc[mf][nf][2], acc[mf][nf][3]);
            }
        }
        return;
    }

    // fused QKV epilogue with RoPE (bn decides segment; 128-wide tiles never cross)
#pragma unroll
    for (int mf = 0; mf < 4; mf++) {
        int row = bm + warpM * 64 + mf * 16 + qr;
        int s0 = row & (SS - 1);
        int s1 = (row + 8) & (SS - 1);
#pragma unroll
        for (int nf = 0; nf < 4; nf++) {
            int col = bn + warpN * 32 + nf * 8 + 2 * qk;
            float a0 = acc[mf][nf][0], a1 = acc[mf][nf][1];
            float b0 = acc[mf][nf][2], b1 = acc[mf][nf][3];
            if (bn < DIMM) {
                // Q: rope -> half
                int d = col & 127;
                float2 f0 = *(const float2*)(fc + (size_t)s0 * 128 + d);
                float2 f1 = *(const float2*)(fc + (size_t)s1 * 128 + d);
                *(__half2*)(qh + (size_t)row * DIMM + col) =
                    __floats2half2_rn(a0 * f0.x - a1 * f0.y, a0 * f0.y + a1 * f0.x);
                *(__half2*)(qh + (size_t)(row + 8) * DIMM + col) =
                    __floats2half2_rn(b0 * f1.x - b1 * f1.y, b0 * f1.y + b1 * f1.x);
            } else if (bn < DIMM + NKVV * HDD) {
                // K: rope -> fp32 new_k + half shadow
                int cc = col - DIMM;
                int d = cc & 127;
                float2 f0 = *(const float2*)(fc + (size_t)s0 * 128 + d);
                float2 f1 = *(const float2*)(fc + (size_t)s1 * 128 + d);
                float o00 = a0 * f0.x - a1 * f0.y, o01 = a0 * f0.y + a1 * f0.x;
                float o10 = b0 * f1.x - b1 * f1.y, o11 = b0 * f1.y + b1 * f1.x;
                *(float2*)(kout + (size_t)row * (NKVV * HDD) + cc) = make_float2(o00, o01);
                *(float2*)(kout + (size_t)(row + 8) * (NKVV * HDD) + cc) = make_float2(o10, o11);
                *(__half2*)(kh + (size_t)row * (NKVV * HDD) + cc) = __floats2half2_rn(o00, o01);
                *(__half2*)(kh + (size_t)(row + 8) * (NKVV * HDD) + cc) = __floats2half2_rn(o10, o11);
            } else {
                // V: fp32 new_v
                int cc = col - DIMM - NKVV * HDD;
                *(float2*)(vout + (size_t)row * (NKVV * HDD) + cc) = make_float2(a0, a1);
                *(float2*)(vout + (size_t)(row + 8) * (NKVV * HDD) + cc) = make_float2(b0, b1);
            }
        }
    }
}

// ----------------------------------------------------------------------------
// FP16 tensor-core flash attention, GQA-shared K/V (proven R10 kernel).
// ----------------------------------------------------------------------------
#define AQS_OFF 0
#define AKS_SZ  (64 * 136)
#define AKS_OFF (64 * 136)
#define AVT_SZ  (128 * 72)
#define AVT_OFF (AKS_OFF + 2 * AKS_SZ)
#define AP_OFF  (AVT_OFF + 2 * AVT_SZ)
#define ATT_SMEM_HALVES (AP_OFF + 64 * 72)   // 49152 halves = 98304 B

__global__ __launch_bounds__(128) void attn_f16_kernel(
    const __half* __restrict__ Q, const __half* __restrict__ K,
    const __half* __restrict__ Vt, __half* __restrict__ O)
{
    extern __shared__ __half smh[];

    const int tid  = threadIdx.x;
    const int lane = tid & 31;
    const int warp = tid >> 5;
    const int qk = lane & 3;
    const int qr = lane >> 2;
    const int r0 = warp * 16 + qr;

    const int qt16 = blockIdx.x;
    const int g = blockIdx.y;
    const int b = blockIdx.z;

    const __half* kbase = K + (size_t)b * SS * (NKVV * HDD) + g * HDD;
    const __half* vtbase = Vt + (size_t)(b * NKVV + g) * HDD * SS;

#pragma unroll
    for (int c = tid; c < 1024; c += 128) {
        int row = c >> 4, cc = c & 15;
        const __half* src = Q + ((size_t)b * SS + qt16 * 16 + (row & 15)) * DIMM
                              + (g * 4 + (row >> 4)) * HDD + cc * 8;
        uint32_t dst = (uint32_t)__cvta_generic_to_shared(smh + AQS_OFF + row * 136 + cc * 8);
        cp_async16(dst, src);
    }
    cp_commit();

    auto load_kv = [&](int t, int st) {
        const __half* kb = kbase + (size_t)t * 64 * (NKVV * HDD);
#pragma unroll
        for (int c = tid; c < 1024; c += 128) {
            int row = c >> 4, cc = c & 15;
            uint32_t dk = (uint32_t)__cvta_generic_to_shared(
                smh + AKS_OFF + st * AKS_SZ + row * 136 + cc * 8);
            cp_async16(dk, kb + (size_t)row * (NKVV * HDD) + cc * 8);
        }
        const __half* vb = vtbase + t * 64;
#pragma unroll
        for (int c = tid; c < 1024; c += 128) {
            int row = c >> 3, cc = c & 7;
            uint32_t dv = (uint32_t)__cvta_generic_to_shared(
                smh + AVT_OFF + st * AVT_SZ + row * 72 + cc * 8);
            cp_async16(dv, vb + (size_t)row * SS + cc * 8);
        }
        cp_commit();
    };

    load_kv(0, 0);
    load_kv(1, 1);
    cp_wait<1>();
    __syncthreads();

    const float scale = 0.08838834764831845f;
    float m0 = -1e30f, m1 = -1e30f, l0 = 0.0f, l1 = 0.0f;
    float oacc[16][4];
#pragma unroll
    for (int nf = 0; nf < 16; nf++)
#pragma unroll
        for (int r = 0; r < 4; r++) oacc[nf][r] = 0.0f;

    const uint32_t* Qw = (const uint32_t*)(smh + AQS_OFF);

    for (int t = 0; t < SS / 64; t++) {
        const int st = t & 1;
        const uint32_t* Kw = (const uint32_t*)(smh + AKS_OFF + st * AKS_SZ);
        const uint32_t* Vw = (const uint32_t*)(smh + AVT_OFF + st * AVT_SZ);
        __half* Ph = smh + AP_OFF;

        float sacc[8][4];
#pragma unroll
        for (int nf = 0; nf < 8; nf++)
#pragma unroll
            for (int r = 0; r < 4; r++) sacc[nf][r] = 0.0f;

#pragma unroll
        for (int kf = 0; kf < 8; kf++) {
            const int kk2 = kf * 8;
            uint32_t a0 = Qw[r0 * 68 + kk2 + qk];
            uint32_t a1 = Qw[(r0 + 8) * 68 + kk2 + qk];
            uint32_t a2 = Qw[r0 * 68 + kk2 + qk + 4];
            uint32_t a3 = Qw[(r0 + 8) * 68 + kk2 + qk + 4];
#pragma unroll
            for (int nf = 0; nf < 8; nf++) {
                int col = nf * 8 + qr;
                uint32_t b0 = Kw[col * 68 + kk2 + qk];
                uint32_t b1 = Kw[col * 68 + kk2 + qk + 4];
                MMA_F16(sacc[nf], a0, a1, a2, a3, b0, b1);
            }
        }

        float mx0 = -1e30f, mx1 = -1e30f;
#pragma unroll
        for (int nf = 0; nf < 8; nf++) {
            mx0 = fmaxf(mx0, fmaxf(sacc[nf][0], sacc[nf][1]));
            mx1 = fmaxf(mx1, fmaxf(sacc[nf][2], sacc[nf][3]));
        }
        mx0 *= scale;
        mx1 *= scale;
        mx0 = fmaxf(mx0, __shfl_xor_sync(0xffffffffu, mx0, 1));
        mx0 = fmaxf(mx0, __shfl_xor_sync(0xffffffffu, mx0, 2));
        mx1 = fmaxf(mx1, __shfl_xor_sync(0xffffffffu, mx1, 1));
        mx1 = fmaxf(mx1, __shfl_xor_sync(0xffffffffu, mx1, 2));

        float mn0 = fmaxf(m0, mx0), mn1 = fmaxf(m1, mx1);
        float cr0 = __expf(m0 - mn0), cr1 = __expf(m1 - mn1);
        float rs0 = 0.0f, rs1 = 0.0f;
#pragma unroll
        for (int nf = 0; nf < 8; nf++) {
            float p00 = __expf(sacc[nf][0] * scale - mn0);
            float p01 = __expf(sacc[nf][1] * scale - mn0);
            float p10 = __expf(sacc[nf][2] * scale - mn1);
            float p11 = __expf(sacc[nf][3] * scale - mn1);
            rs0 += p00 + p01;
            rs1 += p10 + p11;
            *(__half2*)(Ph + r0 * 72 + nf * 8 + 2 * qk)       = __floats2half2_rn(p00, p01);
            *(__half2*)(Ph + (r0 + 8) * 72 + nf * 8 + 2 * qk) = __floats2half2_rn(p10, p11);
        }
        rs0 += __shfl_xor_sync(0xffffffffu, rs0, 1);
        rs0 += __shfl_xor_sync(0xffffffffu, rs0, 2);
        rs1 += __shfl_xor_sync(0xffffffffu, rs1, 1);
        rs1 += __shfl_xor_sync(0xffffffffu, rs1, 2);
        l0 = l0 * cr0 + rs0;
        l1 = l1 * cr1 + rs1;
        m0 = mn0;
        m1 = mn1;
#pragma unroll
        for (int nf = 0; nf < 16; nf++) {
            oacc[nf][0] *= cr0;
            oacc[nf][1] *= cr0;
            oacc[nf][2] *= cr1;
            oacc[nf][3] *= cr1;
        }
        __syncwarp();

        const uint32_t* Pw = (const uint32_t*)(smh + AP_OFF);
#pragma unroll
        for (int kf = 0; kf < 4; kf++) {
            const int kk2 = kf * 8;
            uint32_t a0 = Pw[r0 * 36 + kk2 + qk];
            uint32_t a1 = Pw[(r0 + 8) * 36 + kk2 + qk];
            uint32_t a2 = Pw[r0 * 36 + kk2 + qk + 4];
            uint32_t a3 = Pw[(r0 + 8) * 36 + kk2 + qk + 4];
#pragma unroll
            for (int nf = 0; nf < 16; nf++) {
                int col = nf * 8 + qr;
                uint32_t b0 = Vw[col * 36 + kk2 + qk];
                uint32_t b1 = Vw[col * 36 + kk2 + qk + 4];
                MMA_F16(oacc[nf], a0, a1, a2, a3, b0, b1);
            }
        }

        __syncthreads();
        if (t + 2 < SS / 64) {
            load_kv(t + 2, st);
            cp_wait<1>();
        } else if (t + 1 < SS / 64) {
            cp_wait<0>();
        }
        __syncthreads();
    }

    float inv0 = 1.0f / l0, inv1 = 1.0f / l1;
    __half* obase = O + ((size_t)b * SS + qt16 * 16) * DIMM + (g * 4 + warp) * HDD;
#pragma unroll
    for (int nf = 0; nf < 16; nf++) {
        int col = nf * 8 + 2 * qk;
        __half2* p0 = (__half2*)(obase + (size_t)qr * DIMM + col);
        __half2* p1 = (__half2*)(obase + (size_t)(qr + 8) * DIMM + col);
        *p0 = __floats2half2_rn(oacc[nf][0] * inv0, oacc[nf][1] * inv0);
        *p1 = __floats2half2_rn(oacc[nf][2] * inv1, oacc[nf][3] * inv1);
    }
}

// ----------------------------------------------------------------------------
// Launch
// ----------------------------------------------------------------------------
extern "C" void kernel_launch(void* const* d_in, const int* in_sizes, int n_in,
                              void* d_out, int out_size)
{
    const float* x  = (const float*)d_in[0];
    const float* fc = (const float*)d_in[1];
    const float* wq = (const float*)d_in[2];
    const float* wk = (const float*)d_in[3];
    const float* wv = (const float*)d_in[4];
    const float* wo = (const float*)d_in[5];

    float* out  = (float*)d_out;
    float* kout = out + (size_t)OUT_ELEMS;
    float* vout = kout + (size_t)KV_ELEMS;

    __half *qh, *kh, *vt, *ctxh, *xh, *wqkvh, *woh;
    cudaGetSymbolAddress((void**)&qh, g_qh);
    cudaGetSymbolAddress((void**)&kh, g_kh);
    cudaGetSymbolAddress((void**)&vt, g_vt);
    cudaGetSymbolAddress((void**)&ctxh, g_ctxh);
    cudaGetSymbolAddress((void**)&xh, g_xh);
    cudaGetSymbolAddress((void**)&wqkvh, g_wqkvh);
    cudaGetSymbolAddress((void**)&woh, g_woh);

    // x -> half; weights -> transposed [N][K] half (packed for QKV)
    {
        int n4x = OUT_ELEMS / 4;
        cvt_half_kernel<<<(n4x + 255) / 256, 256>>>(x, xh, n4x);
        dim3 tb(32, 8);
        dim3 tg_q(DIMM / 32, DIMM / 32);
        transpose_cvt_h_kernel<<<tg_q, tb>>>(wq, wqkvh, DIMM, DIMM, 0);
        dim3 tg_kv((NKVV * HDD) / 32, DIMM / 32);
        transpose_cvt_h_kernel<<<tg_kv, tb>>>(wk, wqkvh, DIMM, NKVV * HDD, DIMM);
        transpose_cvt_h_kernel<<<tg_kv, tb>>>(wv, wqkvh, DIMM, NKVV * HDD, DIMM + NKVV * HDD);
        transpose_cvt_h_kernel<<<tg_q, tb>>>(wo, woh, DIMM, DIMM, 0);
    }

    cudaFuncSetAttribute(gemm_f16_kernel,
                         cudaFuncAttributeMaxDynamicSharedMemorySize,
                         GEMM_SMEM_BYTES);

    // Merged Q/K/V projection with fused RoPE epilogue
    {
        dim3 gg(NQKV / 128, MROWS / 128);
        gemm_f16_kernel<<<gg, 256, GEMM_SMEM_BYTES>>>(
            xh, wqkvh, fc,
            qh, kout, kh, vout,
            nullptr,
            MROWS, NQKV, DIMM, 1);
    }

    // V -> transposed half for attention
    {
        dim3 tb(32, 8);
        dim3 tv(SS / 32, HDD / 32, BB * NKVV);
        transpose_v_kernel<<<tv, tb>>>(vout, vt);
    }

    // Attention (fp16 mma flash, GQA-shared K/V) -> half ctx
    {
        size_t smem = ATT_SMEM_HALVES * sizeof(__half);  // 98304 B
        cudaFuncSetAttribute(attn_f16_kernel,
                             cudaFuncAttributeMaxDynamicSharedMemorySize, (int)smem);
        dim3 grid(SS / 16, NKVV, BB);
        attn_f16_kernel<<<grid, 128, smem>>>(qh, kh, vt, ctxh);
    }

    // Output projection (fp16 GEMM, plain epilogue)
    {
        dim3 go(DIMM / 128, MROWS / 128);
        gemm_f16_kernel<<<go, 256, GEMM_SMEM_BYTES>>>(
            ctxh, woh, nullptr,
            nullptr, nullptr, nullptr, nullptr,
            out,
            MROWS, DIMM, DIMM, 0);
    }
}